// round 1
// baseline (speedup 1.0000x reference)
#include <cuda_runtime.h>
#include <math.h>

// Problem constants
#define B_   2
#define S_   2048
#define H_   2048
#define NH_  16
#define NOPE_ 128
#define ROPE_ 64
#define VDIM_ 128
#define RANK_ 512
#define QHD_  192           // NOPE + ROPE
#define DATT_ 576           // RANK + ROPE  (fused attention K-dim)
#define NTOK_ (B_*S_)       // 4096

// ---------------- scratch (static device, allowed) ----------------
__device__ float g_q[(long)NTOK_ * (NH_*QHD_)];          // 4096 x 3072
__device__ float g_ckv[(long)NTOK_ * DATT_];             // 4096 x 576 (raw Wkv_a output)
__device__ float g_kattn[(long)NTOK_ * DATT_];           // 4096 x 576 (rms'd ckv | roped k_pe)
__device__ float g_qattn[(long)B_*NH_*S_ * DATT_];       // 32 x 2048 x 576
__device__ float g_scores[(long)B_*NH_*S_ * S_];         // 32 x 2048 x 2048
__device__ float g_x[(long)B_*NH_*S_ * RANK_];           // 32 x 2048 x 512
__device__ float g_attn[(long)NTOK_ * (NH_*VDIM_)];      // 4096 x 2048

// ---------------- generic batched SGEMM: C = A @ B (or A @ B^T) ----------------
// Tile 64x64, K-tile 16, 256 threads, 4x4 accumulators per thread.
// Per-z offsets: off = (z/zdiv)*Out + (z%zdiv)*In  (applied to A, B, C).
// All M, N multiples of 64; K multiple of 16; all lds & base offsets multiples of 4.
template<bool TRANSB>
__global__ __launch_bounds__(256)
void sgemm(const float* __restrict__ A, const float* __restrict__ B, float* __restrict__ C,
           int M, int N, int K, int lda, int ldb, int ldc,
           int zdiv, long aOut, long aIn, long bOut, long bIn, long cOut, long cIn)
{
    __shared__ float As[16][64];
    __shared__ float Bs[16][64];

    const int z = blockIdx.z;
    A += (long)(z / zdiv) * aOut + (long)(z % zdiv) * aIn;
    B += (long)(z / zdiv) * bOut + (long)(z % zdiv) * bIn;
    C += (long)(z / zdiv) * cOut + (long)(z % zdiv) * cIn;

    const int bm = blockIdx.y * 64;
    const int bn = blockIdx.x * 64;
    const int tid = threadIdx.x;
    const int tx = tid & 15;          // 0..15 (N direction, 4 cols each)
    const int ty = tid >> 4;          // 0..15 (M direction, 4 rows each)
    const int ar = tid >> 2;          // 0..63 row within tile
    const int ac = (tid & 3) * 4;     // 0,4,8,12 k within tile

    float acc[4][4] = {};

    for (int kt = 0; kt < K; kt += 16) {
        // A tile: 64 rows x 16 k, stored transposed As[k][m]
        {
            float4 v = *reinterpret_cast<const float4*>(A + (long)(bm + ar) * lda + kt + ac);
            As[ac + 0][ar] = v.x; As[ac + 1][ar] = v.y;
            As[ac + 2][ar] = v.z; As[ac + 3][ar] = v.w;
        }
        if (TRANSB) {
            // B is (N x K) row-major: tile 64 n x 16 k, stored Bs[k][n]
            float4 v = *reinterpret_cast<const float4*>(B + (long)(bn + ar) * ldb + kt + ac);
            Bs[ac + 0][ar] = v.x; Bs[ac + 1][ar] = v.y;
            Bs[ac + 2][ar] = v.z; Bs[ac + 3][ar] = v.w;
        } else {
            // B is (K x N) row-major: tile 16 k x 64 n
            const int br = tid >> 4;          // 0..15
            const int bc = (tid & 15) * 4;    // 0..60
            float4 v = *reinterpret_cast<const float4*>(B + (long)(kt + br) * ldb + bn + bc);
            *reinterpret_cast<float4*>(&Bs[br][bc]) = v;
        }
        __syncthreads();

#pragma unroll
        for (int kk = 0; kk < 16; kk++) {
            float4 a4 = *reinterpret_cast<const float4*>(&As[kk][ty * 4]);
            float4 b4 = *reinterpret_cast<const float4*>(&Bs[kk][tx * 4]);
            float a[4] = {a4.x, a4.y, a4.z, a4.w};
            float b[4] = {b4.x, b4.y, b4.z, b4.w};
#pragma unroll
            for (int i = 0; i < 4; i++)
#pragma unroll
                for (int j = 0; j < 4; j++)
                    acc[i][j] += a[i] * b[j];
        }
        __syncthreads();
    }

#pragma unroll
    for (int i = 0; i < 4; i++) {
        float4 v = {acc[i][0], acc[i][1], acc[i][2], acc[i][3]};
        *reinterpret_cast<float4*>(C + (long)(bm + ty * 4 + i) * ldc + bn + tx * 4) = v;
    }
}

// ---------------- fused rmsnorm(ckv) + RoPE(k_pe, q_pe) ----------------
// One block per token (128 threads). Writes k_attn[t] = [rms(ckv)*w | rope(k_pe)]
// and q_attn[b,h,s, 512:576] = rope(q_pe[h]) in deinterleaved order.
__global__ __launch_bounds__(128)
void rmsrope_kernel(const float* __restrict__ q,
                    const float* __restrict__ ckv,
                    const int* __restrict__ pos_ids,
                    const float* __restrict__ cosc,
                    const float* __restrict__ sinc,
                    const float* __restrict__ lnw,
                    float* __restrict__ kattn,
                    float* __restrict__ qattn)
{
    const int t = blockIdx.x;            // token 0..4095
    const int b = t / S_;
    const int s = t - b * S_;
    const float* cv = ckv + (long)t * DATT_;
    float* kd = kattn + (long)t * DATT_;

    // --- RMS over first 512 ---
    __shared__ float red[4];
    float ss = 0.f;
    for (int i = threadIdx.x; i < RANK_; i += 128) { float v = cv[i]; ss += v * v; }
#pragma unroll
    for (int o = 16; o; o >>= 1) ss += __shfl_xor_sync(0xffffffffu, ss, o);
    if ((threadIdx.x & 31) == 0) red[threadIdx.x >> 5] = ss;
    __syncthreads();
    const float tot = red[0] + red[1] + red[2] + red[3];
    const float inv = rsqrtf(tot * (1.0f / RANK_) + 1e-6f);

    for (int i = threadIdx.x; i < RANK_; i += 128)
        kd[i] = cv[i] * inv * lnw[i];

    const int pos = pos_ids[t];
    const float* cr = cosc + (long)pos * ROPE_;
    const float* sr = sinc + (long)pos * ROPE_;

    // --- rope k_pe (32 pairs) ---
    if (threadIdx.x < 32) {
        const int j = threadIdx.x;
        const float c = cr[j], sn = sr[j];
        const float e = cv[RANK_ + 2 * j], o = cv[RANK_ + 2 * j + 1];
        kd[RANK_ + j]      = e * c - o * sn;
        kd[RANK_ + 32 + j] = o * c + e * sn;
    }

    // --- rope q_pe for all heads (16 heads x 32 pairs = 512) ---
    for (int p = threadIdx.x; p < NH_ * 32; p += 128) {
        const int h = p >> 5, j = p & 31;
        const float c = cr[j], sn = sr[j];
        const float* qs = q + (long)t * (NH_ * QHD_) + h * QHD_ + NOPE_;
        const float e = qs[2 * j], o = qs[2 * j + 1];
        float* qd = qattn + ((long)(b * NH_ + h) * S_ + s) * DATT_ + RANK_;
        qd[j]      = e * c - o * sn;
        qd[32 + j] = o * c + e * sn;
    }
}

// ---------------- causal softmax (in-place on scores) ----------------
__global__ __launch_bounds__(256)
void softmax_causal(float* __restrict__ sc)
{
    const float scale = 0.07216878364870322f;   // 192^-0.5
    const long row = blockIdx.x;                // 0 .. B*NH*S-1
    const int qi = (int)(row & (S_ - 1));
    float* p = sc + row * (long)S_;
    const int n = qi + 1;

    __shared__ float red[8];
    const int lane = threadIdx.x & 31, wid = threadIdx.x >> 5;

    float m = -1e30f;
    for (int k = threadIdx.x; k < n; k += 256) m = fmaxf(m, p[k] * scale);
#pragma unroll
    for (int o = 16; o; o >>= 1) m = fmaxf(m, __shfl_xor_sync(0xffffffffu, m, o));
    if (lane == 0) red[wid] = m;
    __syncthreads();
    if (threadIdx.x == 0) {
        float mm = red[0];
#pragma unroll
        for (int i = 1; i < 8; i++) mm = fmaxf(mm, red[i]);
        red[0] = mm;
    }
    __syncthreads();
    const float M = red[0];
    __syncthreads();

    float sum = 0.f;
    for (int k = threadIdx.x; k < n; k += 256) {
        float e = __expf(p[k] * scale - M);
        p[k] = e;
        sum += e;
    }
#pragma unroll
    for (int o = 16; o; o >>= 1) sum += __shfl_xor_sync(0xffffffffu, sum, o);
    if (lane == 0) red[wid] = sum;
    __syncthreads();
    if (threadIdx.x == 0) {
        float t = 0.f;
#pragma unroll
        for (int i = 0; i < 8; i++) t += red[i];
        red[0] = 1.0f / t;
    }
    __syncthreads();
    const float invs = red[0];

    for (int k = threadIdx.x; k < n; k += 256) p[k] *= invs;
    for (int k = n + threadIdx.x; k < S_; k += 256) p[k] = 0.f;
}

// ---------------- host side ----------------
static inline void launch_nn(const float* A, const float* Bm, float* C,
                             int M, int N, int K, int lda, int ldb, int ldc,
                             int Z, int zdiv, long aO, long aI, long bO, long bI, long cO, long cI)
{
    dim3 g(N / 64, M / 64, Z);
    sgemm<false><<<g, 256>>>(A, Bm, C, M, N, K, lda, ldb, ldc, zdiv, aO, aI, bO, bI, cO, cI);
}
static inline void launch_nt(const float* A, const float* Bm, float* C,
                             int M, int N, int K, int lda, int ldb, int ldc,
                             int Z, int zdiv, long aO, long aI, long bO, long bI, long cO, long cI)
{
    dim3 g(N / 64, M / 64, Z);
    sgemm<true><<<g, 256>>>(A, Bm, C, M, N, K, lda, ldb, ldc, zdiv, aO, aI, bO, bI, cO, cI);
}

extern "C" void kernel_launch(void* const* d_in, const int* in_sizes, int n_in,
                              void* d_out, int out_size)
{
    const float* hs    = (const float*)d_in[0];
    // d_in[1] = attention_mask (known causal tril) — unused
    const int*   pos   = (const int*)d_in[2];
    const float* cosc  = (const float*)d_in[3];
    const float* sinc  = (const float*)d_in[4];
    const float* Wq    = (const float*)d_in[5];
    const float* Wkv_a = (const float*)d_in[6];
    const float* lnw   = (const float*)d_in[7];
    const float* Wkv_b = (const float*)d_in[8];
    const float* Wo    = (const float*)d_in[9];
    float* out = (float*)d_out;

    float *q, *ckv, *kattn, *qattn, *scores, *x, *attn;
    cudaGetSymbolAddress((void**)&q,      g_q);
    cudaGetSymbolAddress((void**)&ckv,    g_ckv);
    cudaGetSymbolAddress((void**)&kattn,  g_kattn);
    cudaGetSymbolAddress((void**)&qattn,  g_qattn);
    cudaGetSymbolAddress((void**)&scores, g_scores);
    cudaGetSymbolAddress((void**)&x,      g_x);
    cudaGetSymbolAddress((void**)&attn,   g_attn);

    const long sq_bh = (long)S_ * DATT_;        // per-(b,h) q_attn stride
    const long Wb_h  = 256L * RANK_;            // Wkv_b per-head stride

    // 1) q = hs @ Wq                (4096 x 3072, K=2048)
    launch_nn(hs, Wq, q, NTOK_, NH_*QHD_, H_, H_, NH_*QHD_, NH_*QHD_,
              1, 1, 0, 0, 0, 0, 0, 0);

    // 2) ckv_full = hs @ Wkv_a      (4096 x 576, K=2048)
    launch_nn(hs, Wkv_a, ckv, NTOK_, DATT_, H_, H_, DATT_, DATT_,
              1, 1, 0, 0, 0, 0, 0, 0);

    // 3) rms-norm + rope  -> kattn, qattn[...,512:576]
    rmsrope_kernel<<<NTOK_, 128>>>(q, ckv, pos, cosc, sinc, lnw, kattn, qattn);

    // 4) q_nope_c = q_nope @ q_absorb  per (b,h): (2048x128)@(128x512) -> qattn[...,0:512]
    launch_nn(q, Wkv_b, qattn, S_, RANK_, NOPE_,
              NH_*QHD_, RANK_, DATT_,
              B_*NH_, NH_,
              (long)S_*(NH_*QHD_), (long)QHD_,     // A: b outer, h inner
              0, Wb_h,                             // B: Wkv_b[h, 0:128, :]
              (long)NH_*sq_bh, sq_bh);             // C

    // 5) scores = q_attn @ k_attn^T  per (b,h): (2048x576)@(576x2048)
    launch_nt(qattn, kattn, scores, S_, S_, DATT_,
              DATT_, DATT_, S_,
              B_*NH_, NH_,
              (long)NH_*sq_bh, sq_bh,
              (long)S_*DATT_, 0,
              (long)NH_*S_*S_, (long)S_*S_);

    // 6) causal softmax (scale inside)
    softmax_causal<<<B_*NH_*S_, 256>>>(scores);

    // 7) x = probs @ ckv_norm  per (b,h): (2048x2048)@(2048x512), B=kattn[:, :512]
    launch_nn(scores, kattn, x, S_, RANK_, S_,
              S_, DATT_, RANK_,
              B_*NH_, NH_,
              (long)NH_*S_*S_, (long)S_*S_,
              (long)S_*DATT_, 0,
              (long)NH_*S_*RANK_, (long)S_*RANK_);

    // 8) attn = x @ out_absorb^T  per (b,h): (2048x512)@(512x128)^T -> attn[:, h*128:]
    launch_nt(x, Wkv_b + NOPE_*RANK_, attn, S_, VDIM_, RANK_,
              RANK_, RANK_, NH_*VDIM_,
              B_*NH_, NH_,
              (long)NH_*S_*RANK_, (long)S_*RANK_,
              0, Wb_h,
              (long)S_*(NH_*VDIM_), (long)VDIM_);

    // 9) out = attn @ Wo  (4096 x 2048, K=2048)
    launch_nn(attn, Wo, out, NTOK_, H_, NH_*VDIM_, NH_*VDIM_, H_, H_,
              1, 1, 0, 0, 0, 0, 0, 0);
}

// round 3
// speedup vs baseline: 8.2626x; 8.2626x over previous
#include <cuda_runtime.h>
#include <cuda_fp16.h>
#include <math.h>
#include <stdint.h>

// Problem constants
#define B_    2
#define S_    2048
#define H_    2048
#define NH_   16
#define NOPE_ 128
#define ROPE_ 64
#define VDIM_ 128
#define RANK_ 512
#define QHD_  192
#define DATT_ 576
#define NTOK_ (B_*S_)

// ---------------- scratch ----------------
__device__ float g_q[(long)NTOK_ * (NH_*QHD_)];
__device__ float g_ckv[(long)NTOK_ * DATT_];
__device__ float g_kattn[(long)NTOK_ * DATT_];
__device__ float g_qattn[(long)B_*NH_*S_ * DATT_];
__device__ float g_scores[(long)B_*NH_*S_ * S_];
__device__ float g_x[(long)B_*NH_*S_ * RANK_];
__device__ float g_attn[(long)NTOK_ * (NH_*VDIM_)];

__device__ unsigned short g_hs16[(long)NTOK_ * H_];
__device__ unsigned short g_WqT16[(long)(NH_*QHD_) * H_];
__device__ unsigned short g_WkvaT16[(long)DATT_ * H_];
__device__ unsigned short g_WoT16[(long)H_ * (NH_*VDIM_)];
__device__ unsigned short g_qabsT16[(long)NH_ * RANK_ * NOPE_];
__device__ unsigned short g_Wbout16[(long)NH_ * VDIM_ * RANK_];
__device__ unsigned short g_q16[(long)NTOK_ * (NH_*QHD_)];
__device__ unsigned short g_kattn16[(long)NTOK_ * DATT_];
__device__ unsigned short g_ckvT16[(long)B_ * RANK_ * S_];
__device__ unsigned short g_qattn16[(long)B_*NH_*S_ * DATT_];
__device__ unsigned short g_probs16[(long)B_*NH_*S_ * S_];
__device__ unsigned short g_x16[(long)B_*NH_*S_ * RANK_];
__device__ unsigned short g_attn16[(long)NTOK_ * (NH_*VDIM_)];

// ---------------- helpers ----------------
__device__ __forceinline__ uint32_t su32(const void* p){ return (uint32_t)__cvta_generic_to_shared((void*)p); }

#define CP_ASYNC16(dst, src) asm volatile("cp.async.cg.shared.global [%0], [%1], 16;" :: "r"(dst), "l"(src))
#define CP_COMMIT()          asm volatile("cp.async.commit_group;" ::: "memory")
#define CP_WAIT(n)           asm volatile("cp.async.wait_group %0;" :: "n"(n) : "memory")

__device__ __forceinline__ void ldmx4(uint32_t& r0, uint32_t& r1, uint32_t& r2, uint32_t& r3, uint32_t addr){
    asm volatile("ldmatrix.sync.aligned.m8n8.x4.shared.b16 {%0,%1,%2,%3}, [%4];"
                 : "=r"(r0), "=r"(r1), "=r"(r2), "=r"(r3) : "r"(addr));
}
__device__ __forceinline__ void mma16816(float* c, const uint32_t* a, const uint32_t* b){
    asm volatile("mma.sync.aligned.m16n8k16.row.col.f32.f16.f16.f32 "
                 "{%0,%1,%2,%3}, {%4,%5,%6,%7}, {%8,%9}, {%0,%1,%2,%3};"
                 : "+f"(c[0]), "+f"(c[1]), "+f"(c[2]), "+f"(c[3])
                 : "r"(a[0]), "r"(a[1]), "r"(a[2]), "r"(a[3]), "r"(b[0]), "r"(b[1]));
}

// ---------------- HMMA NT GEMM: C(f32) = A(f16,MxK) @ B(f16,NxK)^T ----------------
// CTA tile 128 x BN, K-tile 32, 256 threads (8 warps = 4M x 2N), double-buffered cp.async.
// cmode: 0 = plain, 1 = skip CTA when bn >= bm+128 (causal upper), 2 = clamp K to bm+128.
#define KT_   32
#define PAD_  40     // halfs per smem row (80B stride, ldmatrix conflict-free)

template<int BN>
__global__ __launch_bounds__(256)
void hgemm_mma(const __half* __restrict__ A, const __half* __restrict__ B, float* __restrict__ C,
               int K, int lda, int ldb, int ldc,
               int zdiv, long aOut, long aIn, long bOut, long bIn, long cOut, long cIn,
               int cmode)
{
    constexpr int NT = BN / 16;       // n-atoms per warp (warp tile N = BN/2)
    __shared__ __half sA[2][128 * PAD_];
    __shared__ __half sB[2][BN * PAD_];

    const int bm = blockIdx.y * 128;
    const int bn = blockIdx.x * BN;
    if (cmode == 1 && bn >= bm + 128) return;   // fully-masked score block

    const int z = blockIdx.z;
    A += (long)(z / zdiv) * aOut + (long)(z % zdiv) * aIn;
    B += (long)(z / zdiv) * bOut + (long)(z % zdiv) * bIn;
    C += (long)(z / zdiv) * cOut + (long)(z % zdiv) * cIn;

    const int Keff = (cmode == 2) ? min(K, bm + 128) : K;
    const int NC = Keff / KT_;

    const int tid = threadIdx.x;
    const int lane = tid & 31, wp = tid >> 5;
    const int mw = wp >> 1;                       // 0..3
    const int nw = wp & 1;                        // 0..1
    constexpr int WN = BN / 2;

    // ldmatrix per-lane offsets
    const int arow = mw * 32 + (lane & 15);
    const int acol = (lane >> 4) * 8;
    const int brow = nw * WN + (lane & 7) + ((lane >> 4) << 3);
    const int bcol = ((lane >> 3) & 1) * 8;

    const uint32_t saB[2] = { su32(&sA[0][0]), su32(&sA[1][0]) };
    const uint32_t sbB[2] = { su32(&sB[0][0]), su32(&sB[1][0]) };

    auto load_async = [&](int kt, int s){
        uint32_t sa = saB[s];
#pragma unroll
        for (int i = 0; i < 2; i++) {             // A: 512 x 16B
            int v = tid + i * 256;
            int r = v >> 2, c8 = (v & 3) * 8;
            CP_ASYNC16(sa + (r * PAD_ + c8) * 2,
                       A + (long)(bm + r) * lda + kt + c8);
        }
        uint32_t sb = sbB[s];
#pragma unroll
        for (int i = 0; i < BN / 64; i++) {       // B: BN*4 x 16B
            int v = tid + i * 256;
            int r = v >> 2, c8 = (v & 3) * 8;
            CP_ASYNC16(sb + (r * PAD_ + c8) * 2,
                       B + (long)(bn + r) * ldb + kt + c8);
        }
    };

    float acc[2][NT][4];
#pragma unroll
    for (int mt = 0; mt < 2; mt++)
#pragma unroll
        for (int nt = 0; nt < NT; nt++)
#pragma unroll
            for (int i = 0; i < 4; i++) acc[mt][nt][i] = 0.f;

    load_async(0, 0);
    CP_COMMIT();

    for (int c = 0; c < NC; c++) {
        const int s = c & 1;
        if (c + 1 < NC) { load_async((c + 1) * KT_, s ^ 1); CP_COMMIT(); CP_WAIT(1); }
        else            { CP_WAIT(0); }
        __syncthreads();

#pragma unroll
        for (int kk = 0; kk < KT_; kk += 16) {
            uint32_t afr[2][4];
#pragma unroll
            for (int mt = 0; mt < 2; mt++)
                ldmx4(afr[mt][0], afr[mt][1], afr[mt][2], afr[mt][3],
                      saB[s] + (uint32_t)(((arow + mt * 16) * PAD_ + kk + acol) * 2));
            uint32_t bfr[NT][2];
#pragma unroll
            for (int p = 0; p < NT / 2; p++)
                ldmx4(bfr[2*p][0], bfr[2*p][1], bfr[2*p+1][0], bfr[2*p+1][1],
                      sbB[s] + (uint32_t)(((brow + p * 16) * PAD_ + kk + bcol) * 2));
#pragma unroll
            for (int mt = 0; mt < 2; mt++)
#pragma unroll
                for (int nt = 0; nt < NT; nt++)
                    mma16816(acc[mt][nt], afr[mt], bfr[nt]);
        }
        __syncthreads();
    }

    // epilogue
    const int g = lane >> 2, tg = lane & 3;
#pragma unroll
    for (int mt = 0; mt < 2; mt++) {
        const int row = bm + mw * 32 + mt * 16 + g;
#pragma unroll
        for (int nt = 0; nt < NT; nt++) {
            const int col = bn + nw * WN + nt * 8 + tg * 2;
            *reinterpret_cast<float2*>(C + (long)row * ldc + col)       = make_float2(acc[mt][nt][0], acc[mt][nt][1]);
            *reinterpret_cast<float2*>(C + (long)(row + 8) * ldc + col) = make_float2(acc[mt][nt][2], acc[mt][nt][3]);
        }
    }
}

// ---------------- converts ----------------
__global__ __launch_bounds__(256) void f32tof16(const float* __restrict__ in, __half* __restrict__ out, long n4)
{
    long i = blockIdx.x * 256L + threadIdx.x;
    long stride = (long)gridDim.x * 256;
    for (; i < n4; i += stride) {
        float4 v = reinterpret_cast<const float4*>(in)[i];
        reinterpret_cast<__half2*>(out)[2*i]   = __floats2half2_rn(v.x, v.y);
        reinterpret_cast<__half2*>(out)[2*i+1] = __floats2half2_rn(v.z, v.w);
    }
}

__global__ __launch_bounds__(256) void f32tof16_strided(const float* __restrict__ in, __half* __restrict__ out,
                                                        long chunk4, long inStride4, long n4)
{
    long i = blockIdx.x * 256L + threadIdx.x;
    long stride = (long)gridDim.x * 256;
    for (; i < n4; i += stride) {
        long z = i / chunk4, r = i - z * chunk4;
        float4 v = reinterpret_cast<const float4*>(in)[z * inStride4 + r];
        reinterpret_cast<__half2*>(out)[2*i]   = __floats2half2_rn(v.x, v.y);
        reinterpret_cast<__half2*>(out)[2*i+1] = __floats2half2_rn(v.z, v.w);
    }
}

// out[c][r] = (half) in[r][c]
__global__ __launch_bounds__(256) void transp_f32f16(const float* __restrict__ in, __half* __restrict__ out,
                                                     int ldin, int ldout, long inB, long outB)
{
    __shared__ float t[32][33];
    const int z = blockIdx.z;
    in += (long)z * inB; out += (long)z * outB;
    const int r0 = blockIdx.y * 32, c0 = blockIdx.x * 32;
    const int x = threadIdx.x & 31, y = threadIdx.x >> 5;
#pragma unroll
    for (int i = 0; i < 32; i += 8)
        t[y + i][x] = in[(long)(r0 + y + i) * ldin + c0 + x];
    __syncthreads();
#pragma unroll
    for (int i = 0; i < 32; i += 8)
        out[(long)(c0 + y + i) * ldout + r0 + x] = __float2half_rn(t[x][y + i]);
}

// ---------------- rmsnorm + rope ----------------
__global__ __launch_bounds__(128)
void rmsrope_kernel(const float* __restrict__ q, const float* __restrict__ ckv,
                    const int* __restrict__ pos_ids, const float* __restrict__ cosc,
                    const float* __restrict__ sinc, const float* __restrict__ lnw,
                    float* __restrict__ kattn, float* __restrict__ qattn)
{
    const int t = blockIdx.x;
    const int b = t / S_, s = t - b * S_;
    const float* cv = ckv + (long)t * DATT_;
    float* kd = kattn + (long)t * DATT_;

    __shared__ float red[4];
    float ss = 0.f;
    for (int i = threadIdx.x; i < RANK_; i += 128) { float v = cv[i]; ss += v * v; }
#pragma unroll
    for (int o = 16; o; o >>= 1) ss += __shfl_xor_sync(0xffffffffu, ss, o);
    if ((threadIdx.x & 31) == 0) red[threadIdx.x >> 5] = ss;
    __syncthreads();
    const float inv = rsqrtf((red[0] + red[1] + red[2] + red[3]) * (1.0f / RANK_) + 1e-6f);

    for (int i = threadIdx.x; i < RANK_; i += 128)
        kd[i] = cv[i] * inv * lnw[i];

    const int pos = pos_ids[t];
    const float* cr = cosc + (long)pos * ROPE_;
    const float* sr = sinc + (long)pos * ROPE_;

    if (threadIdx.x < 32) {
        const int j = threadIdx.x;
        const float c = cr[j], sn = sr[j];
        const float e = cv[RANK_ + 2*j], o = cv[RANK_ + 2*j + 1];
        kd[RANK_ + j]      = e * c - o * sn;
        kd[RANK_ + 32 + j] = o * c + e * sn;
    }

    for (int p = threadIdx.x; p < NH_ * 32; p += 128) {
        const int h = p >> 5, j = p & 31;
        const float c = cr[j], sn = sr[j];
        const float* qs = q + (long)t * (NH_*QHD_) + h * QHD_ + NOPE_;
        const float e = qs[2*j], o = qs[2*j + 1];
        float* qd = qattn + ((long)(b * NH_ + h) * S_ + s) * DATT_ + RANK_;
        qd[j]      = e * c - o * sn;
        qd[32 + j] = o * c + e * sn;
    }
}

// ---------------- causal softmax: fp32 scores -> fp16 probs ----------------
__global__ __launch_bounds__(256)
void softmax_causal(const float* __restrict__ sc, __half* __restrict__ pr)
{
    const float scale = 0.07216878364870322f;   // 192^-0.5
    const long row = blockIdx.x;
    const int qi = (int)(row & (S_ - 1));
    const float* p = sc + row * (long)S_;
    __half* o = pr + row * (long)S_;
    const int n = qi + 1;

    __shared__ float red[8];
    const int lane = threadIdx.x & 31, wid = threadIdx.x >> 5;

    float m = -1e30f;
    for (int k = threadIdx.x; k < n; k += 256) m = fmaxf(m, p[k]);
#pragma unroll
    for (int off = 16; off; off >>= 1) m = fmaxf(m, __shfl_xor_sync(0xffffffffu, m, off));
    if (lane == 0) red[wid] = m;
    __syncthreads();
    if (threadIdx.x == 0) {
        float mm = red[0];
#pragma unroll
        for (int i = 1; i < 8; i++) mm = fmaxf(mm, red[i]);
        red[0] = mm;
    }
    __syncthreads();
    const float M = red[0] * scale;
    __syncthreads();

    float sum = 0.f;
    for (int k = threadIdx.x; k < n; k += 256) sum += __expf(p[k] * scale - M);
#pragma unroll
    for (int off = 16; off; off >>= 1) sum += __shfl_xor_sync(0xffffffffu, sum, off);
    if (lane == 0) red[wid] = sum;
    __syncthreads();
    if (threadIdx.x == 0) {
        float t = 0.f;
#pragma unroll
        for (int i = 0; i < 8; i++) t += red[i];
        red[0] = 1.0f / t;
    }
    __syncthreads();
    const float invs = red[0];

    for (int k = threadIdx.x; k < n; k += 256)
        o[k] = __float2half_rn(__expf(p[k] * scale - M) * invs);
    for (int k = n + threadIdx.x; k < S_; k += 256)
        o[k] = __float2half_rn(0.f);
}

// ---------------- host ----------------
static void hgemm(const __half* A, const __half* B, float* C,
                  int M, int N, int K, int lda, int ldb, int ldc, int Z, int zdiv,
                  long aO, long aI, long bO, long bI, long cO, long cI, int cmode = 0)
{
    if (N % 128 == 0) {
        dim3 g(N / 128, M / 128, Z);
        hgemm_mma<128><<<g, 256>>>(A, B, C, K, lda, ldb, ldc, zdiv, aO, aI, bO, bI, cO, cI, cmode);
    } else {
        dim3 g(N / 64, M / 128, Z);
        hgemm_mma<64><<<g, 256>>>(A, B, C, K, lda, ldb, ldc, zdiv, aO, aI, bO, bI, cO, cI, cmode);
    }
}

static void cvt(const float* in, __half* out, long n)
{
    long n4 = n / 4;
    int blocks = (int)((n4 + 255) / 256); if (blocks > 8192) blocks = 8192;
    f32tof16<<<blocks, 256>>>(in, out, n4);
}

extern "C" void kernel_launch(void* const* d_in, const int* in_sizes, int n_in,
                              void* d_out, int out_size)
{
    const float* hs    = (const float*)d_in[0];
    const int*   pos   = (const int*)d_in[2];
    const float* cosc  = (const float*)d_in[3];
    const float* sinc  = (const float*)d_in[4];
    const float* Wq    = (const float*)d_in[5];
    const float* Wkv_a = (const float*)d_in[6];
    const float* lnw   = (const float*)d_in[7];
    const float* Wkv_b = (const float*)d_in[8];
    const float* Wo    = (const float*)d_in[9];
    float* out = (float*)d_out;

    float *q, *ckv, *kattn, *qattn, *scores, *x, *attn;
    cudaGetSymbolAddress((void**)&q, g_q);
    cudaGetSymbolAddress((void**)&ckv, g_ckv);
    cudaGetSymbolAddress((void**)&kattn, g_kattn);
    cudaGetSymbolAddress((void**)&qattn, g_qattn);
    cudaGetSymbolAddress((void**)&scores, g_scores);
    cudaGetSymbolAddress((void**)&x, g_x);
    cudaGetSymbolAddress((void**)&attn, g_attn);

    __half *hs16, *WqT, *WkvaT, *WoT, *qabsT, *Wbout, *q16, *kattn16, *ckvT, *qattn16, *probs16, *x16, *attn16;
    cudaGetSymbolAddress((void**)&hs16, g_hs16);
    cudaGetSymbolAddress((void**)&WqT, g_WqT16);
    cudaGetSymbolAddress((void**)&WkvaT, g_WkvaT16);
    cudaGetSymbolAddress((void**)&WoT, g_WoT16);
    cudaGetSymbolAddress((void**)&qabsT, g_qabsT16);
    cudaGetSymbolAddress((void**)&Wbout, g_Wbout16);
    cudaGetSymbolAddress((void**)&q16, g_q16);
    cudaGetSymbolAddress((void**)&kattn16, g_kattn16);
    cudaGetSymbolAddress((void**)&ckvT, g_ckvT16);
    cudaGetSymbolAddress((void**)&qattn16, g_qattn16);
    cudaGetSymbolAddress((void**)&probs16, g_probs16);
    cudaGetSymbolAddress((void**)&x16, g_x16);
    cudaGetSymbolAddress((void**)&attn16, g_attn16);

    // ---- prep: fp16 + K-major weights ----
    cvt(hs, hs16, (long)NTOK_ * H_);
    {
        transp_f32f16<<<dim3((NH_*QHD_)/32, H_/32, 1), 256>>>(Wq, WqT, NH_*QHD_, H_, 0, 0);
        transp_f32f16<<<dim3(DATT_/32, H_/32, 1), 256>>>(Wkv_a, WkvaT, DATT_, H_, 0, 0);
        transp_f32f16<<<dim3(H_/32, H_/32, 1), 256>>>(Wo, WoT, H_, H_, 0, 0);
        transp_f32f16<<<dim3(RANK_/32, NOPE_/32, NH_), 256>>>(Wkv_b, qabsT, RANK_, NOPE_,
                                                              (long)256*RANK_, (long)RANK_*NOPE_);
        long n4 = (long)NH_ * VDIM_ * RANK_ / 4;
        f32tof16_strided<<<4096, 256>>>(Wkv_b + (long)NOPE_*RANK_, Wbout,
                                        (long)VDIM_*RANK_/4, (long)256*RANK_/4, n4);
    }

    const long sq_bh = (long)S_ * DATT_;

    // 1) q = hs @ Wq
    hgemm(hs16, WqT, q, NTOK_, NH_*QHD_, H_, H_, H_, NH_*QHD_, 1, 1, 0,0,0,0,0,0);
    // 2) ckv = hs @ Wkv_a
    hgemm(hs16, WkvaT, ckv, NTOK_, DATT_, H_, H_, H_, DATT_, 1, 1, 0,0,0,0,0,0);

    // 3) rms + rope
    rmsrope_kernel<<<NTOK_, 128>>>(q, ckv, pos, cosc, sinc, lnw, kattn, qattn);
    cvt(q, q16, (long)NTOK_ * (NH_*QHD_));

    // 4) q_nope_c -> qattn[:, :512]
    hgemm(q16, qabsT, qattn, S_, RANK_, NOPE_, NH_*QHD_, NOPE_, DATT_,
          B_*NH_, NH_,
          (long)S_*(NH_*QHD_), (long)QHD_,
          0, (long)RANK_*NOPE_,
          (long)NH_*sq_bh, sq_bh);

    cvt(kattn, kattn16, (long)NTOK_ * DATT_);
    cvt(qattn, qattn16, (long)B_*NH_*S_ * DATT_);
    transp_f32f16<<<dim3(RANK_/32, S_/32, B_), 256>>>(kattn, ckvT, DATT_, S_,
                                                      (long)S_*DATT_, (long)RANK_*S_);

    // 5) scores = q_attn @ k_attn^T  (skip fully-masked upper blocks)
    hgemm(qattn16, kattn16, scores, S_, S_, DATT_, DATT_, DATT_, S_,
          B_*NH_, NH_,
          (long)NH_*sq_bh, sq_bh,
          (long)S_*DATT_, 0,
          (long)NH_*S_*S_, (long)S_*S_, 1);

    // 6) softmax -> fp16 probs
    softmax_causal<<<B_*NH_*S_, 256>>>(scores, probs16);

    // 7) x = probs @ ckv  (clamp K to causal extent)
    hgemm(probs16, ckvT, x, S_, RANK_, S_, S_, S_, RANK_,
          B_*NH_, NH_,
          (long)NH_*S_*S_, (long)S_*S_,
          (long)RANK_*S_, 0,
          (long)NH_*S_*RANK_, (long)S_*RANK_, 2);

    cvt(x, x16, (long)B_*NH_*S_ * RANK_);

    // 8) attn = x @ out_absorb^T
    hgemm(x16, Wbout, attn, S_, VDIM_, RANK_, RANK_, RANK_, NH_*VDIM_,
          B_*NH_, NH_,
          (long)NH_*S_*RANK_, (long)S_*RANK_,
          0, (long)VDIM_*RANK_,
          (long)S_*(NH_*VDIM_), (long)VDIM_);

    cvt(attn, attn16, (long)NTOK_ * (NH_*VDIM_));

    // 9) out = attn @ Wo
    hgemm(attn16, WoT, out, NTOK_, H_, NH_*VDIM_, NH_*VDIM_, NH_*VDIM_, H_, 1, 1, 0,0,0,0,0,0);
}

// round 4
// speedup vs baseline: 9.7597x; 1.1812x over previous
#include <cuda_runtime.h>
#include <cuda_fp16.h>
#include <math.h>
#include <stdint.h>

// Problem constants
#define B_    2
#define S_    2048
#define H_    2048
#define NH_   16
#define NOPE_ 128
#define ROPE_ 64
#define VDIM_ 128
#define RANK_ 512
#define QHD_  192
#define DATT_ 576
#define NTOK_ (B_*S_)

// ---------------- scratch ----------------
__device__ float g_q[(long)NTOK_ * (NH_*QHD_)];
__device__ float g_ckv[(long)NTOK_ * DATT_];
__device__ float g_scores[(long)B_*NH_*S_ * S_];

__device__ unsigned short g_hs16[(long)NTOK_ * H_];
__device__ unsigned short g_WqT16[(long)(NH_*QHD_) * H_];
__device__ unsigned short g_WkvaT16[(long)DATT_ * H_];
__device__ unsigned short g_WoT16[(long)H_ * (NH_*VDIM_)];
__device__ unsigned short g_qabsT16[(long)NH_ * RANK_ * NOPE_];
__device__ unsigned short g_Wbout16[(long)NH_ * VDIM_ * RANK_];
__device__ unsigned short g_q16[(long)NTOK_ * (NH_*QHD_)];
__device__ unsigned short g_kattn16[(long)NTOK_ * DATT_];
__device__ unsigned short g_ckvT16[(long)B_ * RANK_ * S_];
__device__ unsigned short g_qattn16[(long)B_*NH_*S_ * DATT_];
__device__ unsigned short g_probs16[(long)B_*NH_*S_ * S_];
__device__ unsigned short g_x16[(long)B_*NH_*S_ * RANK_];
__device__ unsigned short g_attn16[(long)NTOK_ * (NH_*VDIM_)];

// ---------------- helpers ----------------
__device__ __forceinline__ uint32_t su32(const void* p){ return (uint32_t)__cvta_generic_to_shared((void*)p); }

#define CP_ASYNC16(dst, src) asm volatile("cp.async.cg.shared.global [%0], [%1], 16;" :: "r"(dst), "l"(src))
#define CP_COMMIT()          asm volatile("cp.async.commit_group;" ::: "memory")
#define CP_WAIT(n)           asm volatile("cp.async.wait_group %0;" :: "n"(n) : "memory")

__device__ __forceinline__ void ldmx4(uint32_t& r0, uint32_t& r1, uint32_t& r2, uint32_t& r3, uint32_t addr){
    asm volatile("ldmatrix.sync.aligned.m8n8.x4.shared.b16 {%0,%1,%2,%3}, [%4];"
                 : "=r"(r0), "=r"(r1), "=r"(r2), "=r"(r3) : "r"(addr));
}
__device__ __forceinline__ void mma16816(float* c, const uint32_t* a, const uint32_t* b){
    asm volatile("mma.sync.aligned.m16n8k16.row.col.f32.f16.f16.f32 "
                 "{%0,%1,%2,%3}, {%4,%5,%6,%7}, {%8,%9}, {%0,%1,%2,%3};"
                 : "+f"(c[0]), "+f"(c[1]), "+f"(c[2]), "+f"(c[3])
                 : "r"(a[0]), "r"(a[1]), "r"(a[2]), "r"(a[3]), "r"(b[0]), "r"(b[1]));
}

// ---------------- HMMA NT GEMM: C = A(f16,MxK) @ B(f16,NxK)^T ----------------
// CTA tile 128 x BN, K-tile 32, 256 threads (8 warps = 4M x 2N), 3-stage cp.async.
// cmode: 0 = plain, 1 = skip CTA when bn >= bm+128 (causal upper), 2 = clamp K to bm+128.
#define KT_   32
#define PAD_  40

template<int BN, typename CT>
__global__ __launch_bounds__(256)
void hgemm_mma(const __half* __restrict__ A, const __half* __restrict__ B, CT* __restrict__ C,
               int K, int lda, int ldb, int ldc,
               int zdiv, long aOut, long aIn, long bOut, long bIn, long cOut, long cIn,
               int cmode)
{
    constexpr int NT = BN / 16;
    constexpr int ASTR = 128 * PAD_ * 2;     // bytes per A stage
    constexpr int BSTR = BN * PAD_ * 2;
    extern __shared__ char smem[];
    const uint32_t saBase = su32(smem);
    const uint32_t sbBase = saBase + 3 * ASTR;

    const int bm = blockIdx.y * 128;
    const int bn = blockIdx.x * BN;
    if (cmode == 1 && bn >= bm + 128) return;

    const int z = blockIdx.z;
    A += (long)(z / zdiv) * aOut + (long)(z % zdiv) * aIn;
    B += (long)(z / zdiv) * bOut + (long)(z % zdiv) * bIn;
    C += (long)(z / zdiv) * cOut + (long)(z % zdiv) * cIn;

    const int Keff = (cmode == 2) ? min(K, bm + 128) : K;
    const int NC = Keff / KT_;

    const int tid = threadIdx.x;
    const int lane = tid & 31, wp = tid >> 5;
    const int mw = wp >> 1;
    const int nw = wp & 1;
    constexpr int WN = BN / 2;

    const int arow = mw * 32 + (lane & 15);
    const int acol = (lane >> 4) * 8;
    const int brow = nw * WN + (lane & 7) + ((lane >> 4) << 3);
    const int bcol = ((lane >> 3) & 1) * 8;

    auto load_async = [&](int kt, int s){
        uint32_t sa = saBase + s * ASTR;
#pragma unroll
        for (int i = 0; i < 2; i++) {
            int v = tid + i * 256;
            int r = v >> 2, c8 = (v & 3) * 8;
            CP_ASYNC16(sa + (r * PAD_ + c8) * 2, A + (long)(bm + r) * lda + kt + c8);
        }
        uint32_t sb = sbBase + s * BSTR;
#pragma unroll
        for (int i = 0; i < BN / 64; i++) {
            int v = tid + i * 256;
            int r = v >> 2, c8 = (v & 3) * 8;
            CP_ASYNC16(sb + (r * PAD_ + c8) * 2, B + (long)(bn + r) * ldb + kt + c8);
        }
    };

    float acc[2][NT][4];
#pragma unroll
    for (int mt = 0; mt < 2; mt++)
#pragma unroll
        for (int nt = 0; nt < NT; nt++)
#pragma unroll
            for (int i = 0; i < 4; i++) acc[mt][nt][i] = 0.f;

    load_async(0, 0);        CP_COMMIT();
    load_async(KT_, 1);      CP_COMMIT();
    CP_WAIT(1);
    __syncthreads();

    for (int c = 0; c < NC; c++) {
        const int s = c - (c / 3) * 3;
        const uint32_t sa = saBase + s * ASTR;
        const uint32_t sb = sbBase + s * BSTR;

#pragma unroll
        for (int kk = 0; kk < KT_; kk += 16) {
            uint32_t afr[2][4];
#pragma unroll
            for (int mt = 0; mt < 2; mt++)
                ldmx4(afr[mt][0], afr[mt][1], afr[mt][2], afr[mt][3],
                      sa + (uint32_t)(((arow + mt * 16) * PAD_ + kk + acol) * 2));
            uint32_t bfr[NT][2];
#pragma unroll
            for (int p = 0; p < NT / 2; p++)
                ldmx4(bfr[2*p][0], bfr[2*p][1], bfr[2*p+1][0], bfr[2*p+1][1],
                      sb + (uint32_t)(((brow + p * 16) * PAD_ + kk + bcol) * 2));
#pragma unroll
            for (int mt = 0; mt < 2; mt++)
#pragma unroll
                for (int nt = 0; nt < NT; nt++)
                    mma16816(acc[mt][nt], afr[mt], bfr[nt]);
        }
        __syncthreads();                       // all warps done with stage s

        if (c + 2 < NC) { load_async((c + 2) * KT_, (c + 2) % 3); CP_COMMIT(); }
        if (c + 1 < NC) {
            if (c + 2 < NC) CP_WAIT(1); else CP_WAIT(0);
            __syncthreads();
        }
    }

    // epilogue
    const int g = lane >> 2, tg = lane & 3;
#pragma unroll
    for (int mt = 0; mt < 2; mt++) {
        const int row = bm + mw * 32 + mt * 16 + g;
#pragma unroll
        for (int nt = 0; nt < NT; nt++) {
            const int col = bn + nw * WN + nt * 8 + tg * 2;
            if constexpr (sizeof(CT) == 2) {
                *reinterpret_cast<__half2*>((__half*)C + (long)row * ldc + col) =
                    __floats2half2_rn(acc[mt][nt][0], acc[mt][nt][1]);
                *reinterpret_cast<__half2*>((__half*)C + (long)(row + 8) * ldc + col) =
                    __floats2half2_rn(acc[mt][nt][2], acc[mt][nt][3]);
            } else {
                *reinterpret_cast<float2*>((float*)C + (long)row * ldc + col) =
                    make_float2(acc[mt][nt][0], acc[mt][nt][1]);
                *reinterpret_cast<float2*>((float*)C + (long)(row + 8) * ldc + col) =
                    make_float2(acc[mt][nt][2], acc[mt][nt][3]);
            }
        }
    }
}

// ---------------- converts ----------------
__global__ __launch_bounds__(256) void f32tof16(const float* __restrict__ in, __half* __restrict__ out, long n4)
{
    long i = blockIdx.x * 256L + threadIdx.x;
    long stride = (long)gridDim.x * 256;
    for (; i < n4; i += stride) {
        float4 v = reinterpret_cast<const float4*>(in)[i];
        reinterpret_cast<__half2*>(out)[2*i]   = __floats2half2_rn(v.x, v.y);
        reinterpret_cast<__half2*>(out)[2*i+1] = __floats2half2_rn(v.z, v.w);
    }
}

__global__ __launch_bounds__(256) void f32tof16_strided(const float* __restrict__ in, __half* __restrict__ out,
                                                        long chunk4, long inStride4, long n4)
{
    long i = blockIdx.x * 256L + threadIdx.x;
    long stride = (long)gridDim.x * 256;
    for (; i < n4; i += stride) {
        long z = i / chunk4, r = i - z * chunk4;
        float4 v = reinterpret_cast<const float4*>(in)[z * inStride4 + r];
        reinterpret_cast<__half2*>(out)[2*i]   = __floats2half2_rn(v.x, v.y);
        reinterpret_cast<__half2*>(out)[2*i+1] = __floats2half2_rn(v.z, v.w);
    }
}

// out[c][r] = (half) in[r][c]   (f32 input)
__global__ __launch_bounds__(256) void transp_f32f16(const float* __restrict__ in, __half* __restrict__ out,
                                                     int ldin, int ldout, long inB, long outB)
{
    __shared__ float t[32][33];
    const int z = blockIdx.z;
    in += (long)z * inB; out += (long)z * outB;
    const int r0 = blockIdx.y * 32, c0 = blockIdx.x * 32;
    const int x = threadIdx.x & 31, y = threadIdx.x >> 5;
#pragma unroll
    for (int i = 0; i < 32; i += 8)
        t[y + i][x] = in[(long)(r0 + y + i) * ldin + c0 + x];
    __syncthreads();
#pragma unroll
    for (int i = 0; i < 32; i += 8)
        out[(long)(c0 + y + i) * ldout + r0 + x] = __float2half_rn(t[x][y + i]);
}

// out[c][r] = in[r][c]   (f16 -> f16)
__global__ __launch_bounds__(256) void transp_f16(const __half* __restrict__ in, __half* __restrict__ out,
                                                  int ldin, int ldout, long inB, long outB)
{
    __shared__ __half t[32][34];
    const int z = blockIdx.z;
    in += (long)z * inB; out += (long)z * outB;
    const int r0 = blockIdx.y * 32, c0 = blockIdx.x * 32;
    const int x = threadIdx.x & 31, y = threadIdx.x >> 5;
#pragma unroll
    for (int i = 0; i < 32; i += 8)
        t[y + i][x] = in[(long)(r0 + y + i) * ldin + c0 + x];
    __syncthreads();
#pragma unroll
    for (int i = 0; i < 32; i += 8)
        out[(long)(c0 + y + i) * ldout + r0 + x] = t[x][y + i];
}

// ---------------- rmsnorm + rope (fp16 outputs) ----------------
__global__ __launch_bounds__(128)
void rmsrope_kernel(const float* __restrict__ q, const float* __restrict__ ckv,
                    const int* __restrict__ pos_ids, const float* __restrict__ cosc,
                    const float* __restrict__ sinc, const float* __restrict__ lnw,
                    __half* __restrict__ kattn, __half* __restrict__ qattn)
{
    const int t = blockIdx.x;
    const int b = t / S_, s = t - b * S_;
    const float* cv = ckv + (long)t * DATT_;
    __half* kd = kattn + (long)t * DATT_;

    __shared__ float red[4];
    float ss = 0.f;
    for (int i = threadIdx.x; i < RANK_; i += 128) { float v = cv[i]; ss += v * v; }
#pragma unroll
    for (int o = 16; o; o >>= 1) ss += __shfl_xor_sync(0xffffffffu, ss, o);
    if ((threadIdx.x & 31) == 0) red[threadIdx.x >> 5] = ss;
    __syncthreads();
    const float inv = rsqrtf((red[0] + red[1] + red[2] + red[3]) * (1.0f / RANK_) + 1e-6f);

    for (int i = threadIdx.x; i < RANK_; i += 128)
        kd[i] = __float2half_rn(cv[i] * inv * lnw[i]);

    const int pos = pos_ids[t];
    const float* cr = cosc + (long)pos * ROPE_;
    const float* sr = sinc + (long)pos * ROPE_;

    if (threadIdx.x < 32) {
        const int j = threadIdx.x;
        const float c = cr[j], sn = sr[j];
        const float e = cv[RANK_ + 2*j], o = cv[RANK_ + 2*j + 1];
        kd[RANK_ + j]      = __float2half_rn(e * c - o * sn);
        kd[RANK_ + 32 + j] = __float2half_rn(o * c + e * sn);
    }

    for (int p = threadIdx.x; p < NH_ * 32; p += 128) {
        const int h = p >> 5, j = p & 31;
        const float c = cr[j], sn = sr[j];
        const float* qs = q + (long)t * (NH_*QHD_) + h * QHD_ + NOPE_;
        const float e = qs[2*j], o = qs[2*j + 1];
        __half* qd = qattn + ((long)(b * NH_ + h) * S_ + s) * DATT_ + RANK_;
        qd[j]      = __float2half_rn(e * c - o * sn);
        qd[32 + j] = __float2half_rn(o * c + e * sn);
    }
}

// ---------------- causal softmax: 1-pass smem-cached, fp16 probs ----------------
__global__ __launch_bounds__(256)
void softmax_causal(const float* __restrict__ sc, __half* __restrict__ pr)
{
    const float scale = 0.07216878364870322f;   // 192^-0.5
    __shared__ float buf[S_];
    __shared__ float red[8];
    const long row = blockIdx.x;
    const int qi = (int)(row & (S_ - 1));
    const float* p = sc + row * (long)S_;
    __half* o = pr + row * (long)S_;
    const int n = qi + 1;
    const int nend = ((qi >> 7) + 1) << 7;       // PV GEMM reads only up to here

    const int lane = threadIdx.x & 31, wid = threadIdx.x >> 5;

    float m = -1e30f;
    for (int k = threadIdx.x; k < n; k += 256) { float v = p[k]; buf[k] = v; m = fmaxf(m, v); }
#pragma unroll
    for (int off = 16; off; off >>= 1) m = fmaxf(m, __shfl_xor_sync(0xffffffffu, m, off));
    if (lane == 0) red[wid] = m;
    __syncthreads();
    if (threadIdx.x == 0) {
        float mm = red[0];
#pragma unroll
        for (int i = 1; i < 8; i++) mm = fmaxf(mm, red[i]);
        red[0] = mm;
    }
    __syncthreads();
    const float M = red[0] * scale;
    __syncthreads();

    float sum = 0.f;
    for (int k = threadIdx.x; k < n; k += 256) {
        float e = __expf(buf[k] * scale - M);
        buf[k] = e;
        sum += e;
    }
#pragma unroll
    for (int off = 16; off; off >>= 1) sum += __shfl_xor_sync(0xffffffffu, sum, off);
    if (lane == 0) red[wid] = sum;
    __syncthreads();
    if (threadIdx.x == 0) {
        float t = 0.f;
#pragma unroll
        for (int i = 0; i < 8; i++) t += red[i];
        red[0] = 1.0f / t;
    }
    __syncthreads();
    const float invs = red[0];

    for (int k = threadIdx.x; k < n; k += 256)
        o[k] = __float2half_rn(buf[k] * invs);
    for (int k = n + threadIdx.x; k < nend; k += 256)
        o[k] = __float2half_rn(0.f);
}

// ---------------- host ----------------
template<typename CT>
static void hgemm_t(const __half* A, const __half* B, CT* C,
                    int M, int N, int K, int lda, int ldb, int ldc, int Z, int zdiv,
                    long aO, long aI, long bO, long bI, long cO, long cI, int cmode)
{
    if (N % 128 == 0) {
        int sm = 3 * 128 * PAD_ * 2 + 3 * 128 * PAD_ * 2;   // 61440
        cudaFuncSetAttribute(hgemm_mma<128, CT>, cudaFuncAttributeMaxDynamicSharedMemorySize, sm);
        dim3 g(N / 128, M / 128, Z);
        hgemm_mma<128, CT><<<g, 256, sm>>>(A, B, C, K, lda, ldb, ldc, zdiv, aO, aI, bO, bI, cO, cI, cmode);
    } else {
        int sm = 3 * 128 * PAD_ * 2 + 3 * 64 * PAD_ * 2;    // 46080
        cudaFuncSetAttribute(hgemm_mma<64, CT>, cudaFuncAttributeMaxDynamicSharedMemorySize, sm);
        dim3 g(N / 64, M / 128, Z);
        hgemm_mma<64, CT><<<g, 256, sm>>>(A, B, C, K, lda, ldb, ldc, zdiv, aO, aI, bO, bI, cO, cI, cmode);
    }
}

static void cvt(const float* in, __half* out, long n)
{
    long n4 = n / 4;
    int blocks = (int)((n4 + 255) / 256); if (blocks > 8192) blocks = 8192;
    f32tof16<<<blocks, 256>>>(in, out, n4);
}

extern "C" void kernel_launch(void* const* d_in, const int* in_sizes, int n_in,
                              void* d_out, int out_size)
{
    const float* hs    = (const float*)d_in[0];
    const int*   pos   = (const int*)d_in[2];
    const float* cosc  = (const float*)d_in[3];
    const float* sinc  = (const float*)d_in[4];
    const float* Wq    = (const float*)d_in[5];
    const float* Wkv_a = (const float*)d_in[6];
    const float* lnw   = (const float*)d_in[7];
    const float* Wkv_b = (const float*)d_in[8];
    const float* Wo    = (const float*)d_in[9];
    float* out = (float*)d_out;

    float *q, *ckv, *scores;
    cudaGetSymbolAddress((void**)&q, g_q);
    cudaGetSymbolAddress((void**)&ckv, g_ckv);
    cudaGetSymbolAddress((void**)&scores, g_scores);

    __half *hs16, *WqT, *WkvaT, *WoT, *qabsT, *Wbout, *q16, *kattn16, *ckvT, *qattn16, *probs16, *x16, *attn16;
    cudaGetSymbolAddress((void**)&hs16, g_hs16);
    cudaGetSymbolAddress((void**)&WqT, g_WqT16);
    cudaGetSymbolAddress((void**)&WkvaT, g_WkvaT16);
    cudaGetSymbolAddress((void**)&WoT, g_WoT16);
    cudaGetSymbolAddress((void**)&qabsT, g_qabsT16);
    cudaGetSymbolAddress((void**)&Wbout, g_Wbout16);
    cudaGetSymbolAddress((void**)&q16, g_q16);
    cudaGetSymbolAddress((void**)&kattn16, g_kattn16);
    cudaGetSymbolAddress((void**)&ckvT, g_ckvT16);
    cudaGetSymbolAddress((void**)&qattn16, g_qattn16);
    cudaGetSymbolAddress((void**)&probs16, g_probs16);
    cudaGetSymbolAddress((void**)&x16, g_x16);
    cudaGetSymbolAddress((void**)&attn16, g_attn16);

    // ---- prep: fp16 + K-major weights ----
    cvt(hs, hs16, (long)NTOK_ * H_);
    {
        transp_f32f16<<<dim3((NH_*QHD_)/32, H_/32, 1), 256>>>(Wq, WqT, NH_*QHD_, H_, 0, 0);
        transp_f32f16<<<dim3(DATT_/32, H_/32, 1), 256>>>(Wkv_a, WkvaT, DATT_, H_, 0, 0);
        transp_f32f16<<<dim3(H_/32, H_/32, 1), 256>>>(Wo, WoT, H_, H_, 0, 0);
        transp_f32f16<<<dim3(RANK_/32, NOPE_/32, NH_), 256>>>(Wkv_b, qabsT, RANK_, NOPE_,
                                                              (long)256*RANK_, (long)RANK_*NOPE_);
        long n4 = (long)NH_ * VDIM_ * RANK_ / 4;
        f32tof16_strided<<<4096, 256>>>(Wkv_b + (long)NOPE_*RANK_, Wbout,
                                        (long)VDIM_*RANK_/4, (long)256*RANK_/4, n4);
    }

    const long sq_bh = (long)S_ * DATT_;

    // 1) q = hs @ Wq   (fp32 out, rope needs it)
    hgemm_t<float>(hs16, WqT, q, NTOK_, NH_*QHD_, H_, H_, H_, NH_*QHD_, 1, 1, 0,0,0,0,0,0, 0);
    // 2) ckv = hs @ Wkv_a  (fp32 out, rmsnorm needs it)
    hgemm_t<float>(hs16, WkvaT, ckv, NTOK_, DATT_, H_, H_, H_, DATT_, 1, 1, 0,0,0,0,0,0, 0);

    // 3) rms + rope -> kattn16, qattn16[...,512:]
    rmsrope_kernel<<<NTOK_, 128>>>(q, ckv, pos, cosc, sinc, lnw, kattn16, qattn16);
    cvt(q, q16, (long)NTOK_ * (NH_*QHD_));

    // 4) q_nope_c -> qattn16[:, :512]   (fp16 out)
    hgemm_t<__half>(q16, qabsT, qattn16, S_, RANK_, NOPE_, NH_*QHD_, NOPE_, DATT_,
          B_*NH_, NH_,
          (long)S_*(NH_*QHD_), (long)QHD_,
          0, (long)RANK_*NOPE_,
          (long)NH_*sq_bh, sq_bh, 0);

    // ckv^T per batch (fp16 -> fp16)
    transp_f16<<<dim3(RANK_/32, S_/32, B_), 256>>>(kattn16, ckvT, DATT_, S_,
                                                   (long)S_*DATT_, (long)RANK_*S_);

    // 5) scores = q_attn @ k_attn^T (causal block skip, fp32 out)
    hgemm_t<float>(qattn16, kattn16, scores, S_, S_, DATT_, DATT_, DATT_, S_,
          B_*NH_, NH_,
          (long)NH_*sq_bh, sq_bh,
          (long)S_*DATT_, 0,
          (long)NH_*S_*S_, (long)S_*S_, 1);

    // 6) softmax -> fp16 probs (zero-fill only to 128-multiple)
    softmax_causal<<<B_*NH_*S_, 256>>>(scores, probs16);

    // 7) x = probs @ ckv (K clamped, fp16 out)
    hgemm_t<__half>(probs16, ckvT, x16, S_, RANK_, S_, S_, S_, RANK_,
          B_*NH_, NH_,
          (long)NH_*S_*S_, (long)S_*S_,
          (long)RANK_*S_, 0,
          (long)NH_*S_*RANK_, (long)S_*RANK_, 2);

    // 8) attn = x @ out_absorb^T (fp16 out)
    hgemm_t<__half>(x16, Wbout, attn16, S_, VDIM_, RANK_, RANK_, RANK_, NH_*VDIM_,
          B_*NH_, NH_,
          (long)NH_*S_*RANK_, (long)S_*RANK_,
          0, (long)VDIM_*RANK_,
          (long)S_*(NH_*VDIM_), (long)VDIM_, 0);

    // 9) out = attn @ Wo (fp32 final)
    hgemm_t<float>(attn16, WoT, out, NTOK_, H_, NH_*VDIM_, NH_*VDIM_, NH_*VDIM_, H_, 1, 1, 0,0,0,0,0,0, 0);
}

// round 5
// speedup vs baseline: 11.4754x; 1.1758x over previous
#include <cuda_runtime.h>
#include <cuda_fp16.h>
#include <math.h>
#include <stdint.h>

// Problem constants
#define B_    2
#define S_    2048
#define H_    2048
#define NH_   16
#define NOPE_ 128
#define ROPE_ 64
#define VDIM_ 128
#define RANK_ 512
#define QHD_  192
#define DATT_ 576
#define NTOK_ (B_*S_)

// ---------------- scratch ----------------
__device__ float g_scores[(long)B_*NH_*S_ * S_];

__device__ unsigned short g_hs16[(long)NTOK_ * H_];
__device__ unsigned short g_WqT16[(long)(NH_*QHD_) * H_];
__device__ unsigned short g_WkvaT16[(long)DATT_ * H_];
__device__ unsigned short g_WoT16[(long)H_ * (NH_*VDIM_)];
__device__ unsigned short g_Wkvb16[(long)NH_ * 256 * RANK_];
__device__ unsigned short g_q16[(long)NTOK_ * (NH_*QHD_)];       // roped in place
__device__ unsigned short g_ckvraw16[(long)NTOK_ * DATT_];
__device__ unsigned short g_ckv16[(long)NTOK_ * RANK_];          // rms-normed
__device__ unsigned short g_keff16[(long)B_*NH_*S_ * QHD_];      // [ckv@qabs^T | k_pe]
__device__ unsigned short g_ckvT16[(long)B_ * RANK_ * S_];
__device__ unsigned short g_probs16[(long)B_*NH_*S_ * S_];
__device__ unsigned short g_x16[(long)B_*NH_*S_ * RANK_];
__device__ unsigned short g_attn16[(long)NTOK_ * (NH_*VDIM_)];

// ---------------- helpers ----------------
__device__ __forceinline__ uint32_t su32(const void* p){ return (uint32_t)__cvta_generic_to_shared((void*)p); }

#define CP_ASYNC16(dst, src) asm volatile("cp.async.cg.shared.global [%0], [%1], 16;" :: "r"(dst), "l"(src))
#define CP_COMMIT()          asm volatile("cp.async.commit_group;" ::: "memory")
#define CP_WAIT(n)           asm volatile("cp.async.wait_group %0;" :: "n"(n) : "memory")

__device__ __forceinline__ void ldmx4(uint32_t& r0, uint32_t& r1, uint32_t& r2, uint32_t& r3, uint32_t addr){
    asm volatile("ldmatrix.sync.aligned.m8n8.x4.shared.b16 {%0,%1,%2,%3}, [%4];"
                 : "=r"(r0), "=r"(r1), "=r"(r2), "=r"(r3) : "r"(addr));
}
__device__ __forceinline__ void mma16816(float* c, const uint32_t* a, const uint32_t* b){
    asm volatile("mma.sync.aligned.m16n8k16.row.col.f32.f16.f16.f32 "
                 "{%0,%1,%2,%3}, {%4,%5,%6,%7}, {%8,%9}, {%0,%1,%2,%3};"
                 : "+f"(c[0]), "+f"(c[1]), "+f"(c[2]), "+f"(c[3])
                 : "r"(a[0]), "r"(a[1]), "r"(a[2]), "r"(a[3]), "r"(b[0]), "r"(b[1]));
}

// ---------------- HMMA NT GEMM: C = A(f16,MxK) @ B(f16,NxK)^T ----------------
// CTA tile 128 x BN, K-tile 32, 256 threads (8 warps = 4M x 2N), 3-stage cp.async,
// one __syncthreads per mainloop iteration.
// cmode: 0 = plain, 1 = skip CTA when bn >= bm+128 (causal upper), 2 = clamp K to bm+128.
#define KT_   32
#define PAD_  40

template<int BN, typename CT>
__global__ __launch_bounds__(256)
void hgemm_mma(const __half* __restrict__ A, const __half* __restrict__ B, CT* __restrict__ C,
               int K, int lda, int ldb, int ldc,
               int zdiv, long aOut, long aIn, long bOut, long bIn, long cOut, long cIn,
               int cmode)
{
    constexpr int NT = BN / 16;
    constexpr int ASTR = 128 * PAD_ * 2;
    constexpr int BSTR = BN * PAD_ * 2;
    extern __shared__ char smem[];
    const uint32_t saBase = su32(smem);
    const uint32_t sbBase = saBase + 3 * ASTR;

    const int bm = blockIdx.y * 128;
    const int bn = blockIdx.x * BN;
    if (cmode == 1 && bn >= bm + 128) return;

    const int z = blockIdx.z;
    A += (long)(z / zdiv) * aOut + (long)(z % zdiv) * aIn;
    B += (long)(z / zdiv) * bOut + (long)(z % zdiv) * bIn;
    C += (long)(z / zdiv) * cOut + (long)(z % zdiv) * cIn;

    const int Keff = (cmode == 2) ? min(K, bm + 128) : K;
    const int NC = Keff / KT_;

    const int tid = threadIdx.x;
    const int lane = tid & 31, wp = tid >> 5;
    const int mw = wp >> 1;
    const int nw = wp & 1;
    constexpr int WN = BN / 2;

    const int arow = mw * 32 + (lane & 15);
    const int acol = (lane >> 4) * 8;
    const int brow = nw * WN + (lane & 7) + ((lane >> 4) << 3);
    const int bcol = ((lane >> 3) & 1) * 8;

    auto load_async = [&](int kt, int s){
        uint32_t sa = saBase + s * ASTR;
#pragma unroll
        for (int i = 0; i < 2; i++) {
            int v = tid + i * 256;
            int r = v >> 2, c8 = (v & 3) * 8;
            CP_ASYNC16(sa + (r * PAD_ + c8) * 2, A + (long)(bm + r) * lda + kt + c8);
        }
        uint32_t sb = sbBase + s * BSTR;
#pragma unroll
        for (int i = 0; i < BN / 64; i++) {
            int v = tid + i * 256;
            int r = v >> 2, c8 = (v & 3) * 8;
            CP_ASYNC16(sb + (r * PAD_ + c8) * 2, B + (long)(bn + r) * ldb + kt + c8);
        }
    };

    float acc[2][NT][4];
#pragma unroll
    for (int mt = 0; mt < 2; mt++)
#pragma unroll
        for (int nt = 0; nt < NT; nt++)
#pragma unroll
            for (int i = 0; i < 4; i++) acc[mt][nt][i] = 0.f;

    load_async(0, 0);  CP_COMMIT();
    if (NC > 1) load_async(KT_, 1);
    CP_COMMIT();

    for (int c = 0; c < NC; c++) {
        if (c == NC - 1) { CP_WAIT(0); } else { CP_WAIT(1); }
        __syncthreads();
        if (c + 2 < NC) { load_async((c + 2) * KT_, (c + 2) % 3); CP_COMMIT(); }

        const int s = c - (c / 3) * 3;
        const uint32_t sa = saBase + s * ASTR;
        const uint32_t sb = sbBase + s * BSTR;

#pragma unroll
        for (int kk = 0; kk < KT_; kk += 16) {
            uint32_t afr[2][4];
#pragma unroll
            for (int mt = 0; mt < 2; mt++)
                ldmx4(afr[mt][0], afr[mt][1], afr[mt][2], afr[mt][3],
                      sa + (uint32_t)(((arow + mt * 16) * PAD_ + kk + acol) * 2));
            uint32_t bfr[NT][2];
#pragma unroll
            for (int p = 0; p < NT / 2; p++)
                ldmx4(bfr[2*p][0], bfr[2*p][1], bfr[2*p+1][0], bfr[2*p+1][1],
                      sb + (uint32_t)(((brow + p * 16) * PAD_ + kk + bcol) * 2));
#pragma unroll
            for (int mt = 0; mt < 2; mt++)
#pragma unroll
                for (int nt = 0; nt < NT; nt++)
                    mma16816(acc[mt][nt], afr[mt], bfr[nt]);
        }
    }

    // epilogue
    const int g = lane >> 2, tg = lane & 3;
#pragma unroll
    for (int mt = 0; mt < 2; mt++) {
        const int row = bm + mw * 32 + mt * 16 + g;
#pragma unroll
        for (int nt = 0; nt < NT; nt++) {
            const int col = bn + nw * WN + nt * 8 + tg * 2;
            if constexpr (sizeof(CT) == 2) {
                *reinterpret_cast<__half2*>((__half*)C + (long)row * ldc + col) =
                    __floats2half2_rn(acc[mt][nt][0], acc[mt][nt][1]);
                *reinterpret_cast<__half2*>((__half*)C + (long)(row + 8) * ldc + col) =
                    __floats2half2_rn(acc[mt][nt][2], acc[mt][nt][3]);
            } else {
                *reinterpret_cast<float2*>((float*)C + (long)row * ldc + col) =
                    make_float2(acc[mt][nt][0], acc[mt][nt][1]);
                *reinterpret_cast<float2*>((float*)C + (long)(row + 8) * ldc + col) =
                    make_float2(acc[mt][nt][2], acc[mt][nt][3]);
            }
        }
    }
}

// ---------------- converts ----------------
__global__ __launch_bounds__(256) void f32tof16(const float* __restrict__ in, __half* __restrict__ out, long n4)
{
    long i = blockIdx.x * 256L + threadIdx.x;
    long stride = (long)gridDim.x * 256;
    for (; i < n4; i += stride) {
        float4 v = reinterpret_cast<const float4*>(in)[i];
        reinterpret_cast<__half2*>(out)[2*i]   = __floats2half2_rn(v.x, v.y);
        reinterpret_cast<__half2*>(out)[2*i+1] = __floats2half2_rn(v.z, v.w);
    }
}

// out[c][r] = (half) in[r][c]   (f32 input)
__global__ __launch_bounds__(256) void transp_f32f16(const float* __restrict__ in, __half* __restrict__ out,
                                                     int ldin, int ldout, long inB, long outB)
{
    __shared__ float t[32][33];
    const int z = blockIdx.z;
    in += (long)z * inB; out += (long)z * outB;
    const int r0 = blockIdx.y * 32, c0 = blockIdx.x * 32;
    const int x = threadIdx.x & 31, y = threadIdx.x >> 5;
#pragma unroll
    for (int i = 0; i < 32; i += 8)
        t[y + i][x] = in[(long)(r0 + y + i) * ldin + c0 + x];
    __syncthreads();
#pragma unroll
    for (int i = 0; i < 32; i += 8)
        out[(long)(c0 + y + i) * ldout + r0 + x] = __float2half_rn(t[x][y + i]);
}

// out[c][r] = in[r][c]   (f16 -> f16)
__global__ __launch_bounds__(256) void transp_f16(const __half* __restrict__ in, __half* __restrict__ out,
                                                  int ldin, int ldout, long inB, long outB)
{
    __shared__ __half t[32][34];
    const int z = blockIdx.z;
    in += (long)z * inB; out += (long)z * outB;
    const int r0 = blockIdx.y * 32, c0 = blockIdx.x * 32;
    const int x = threadIdx.x & 31, y = threadIdx.x >> 5;
#pragma unroll
    for (int i = 0; i < 32; i += 8)
        t[y + i][x] = in[(long)(r0 + y + i) * ldin + c0 + x];
    __syncthreads();
#pragma unroll
    for (int i = 0; i < 32; i += 8)
        out[(long)(c0 + y + i) * ldout + r0 + x] = t[x][y + i];
}

// ---------------- rmsnorm + rope (all fp16 tensors) ----------------
// Writes: ckv16 = rms(ckv)*w ; keff[b,h,s,128:192] = roped k_pe (all heads) ;
//         q16 q_pe slots roped IN PLACE (deinterleaved).
__global__ __launch_bounds__(128)
void rmsrope_kernel(__half* __restrict__ q16, const __half* __restrict__ ckvraw,
                    const int* __restrict__ pos_ids, const float* __restrict__ cosc,
                    const float* __restrict__ sinc, const float* __restrict__ lnw,
                    __half* __restrict__ ckv16, __half* __restrict__ keff)
{
    const int t = blockIdx.x;
    const int b = t / S_, s = t - b * S_;
    const __half* cv = ckvraw + (long)t * DATT_;

    __shared__ float red[4];
    float ss = 0.f;
    for (int i = threadIdx.x; i < RANK_; i += 128) { float v = __half2float(cv[i]); ss += v * v; }
#pragma unroll
    for (int o = 16; o; o >>= 1) ss += __shfl_xor_sync(0xffffffffu, ss, o);
    if ((threadIdx.x & 31) == 0) red[threadIdx.x >> 5] = ss;
    __syncthreads();
    const float inv = rsqrtf((red[0] + red[1] + red[2] + red[3]) * (1.0f / RANK_) + 1e-6f);

    __half* kd = ckv16 + (long)t * RANK_;
    for (int i = threadIdx.x; i < RANK_; i += 128)
        kd[i] = __float2half_rn(__half2float(cv[i]) * inv * lnw[i]);

    const int pos = pos_ids[t];
    const float* cr = cosc + (long)pos * ROPE_;
    const float* sr = sinc + (long)pos * ROPE_;

    // k_pe rope -> replicate into every head's keff row
    if (threadIdx.x < 32) {
        const int j = threadIdx.x;
        const float c = cr[j], sn = sr[j];
        const float e = __half2float(cv[RANK_ + 2*j]), o = __half2float(cv[RANK_ + 2*j + 1]);
        const __half r0 = __float2half_rn(e * c - o * sn);
        const __half r1 = __float2half_rn(o * c + e * sn);
#pragma unroll
        for (int h = 0; h < NH_; h++) {
            __half* kb = keff + ((long)(b * NH_ + h) * S_ + s) * QHD_ + NOPE_;
            kb[j] = r0; kb[32 + j] = r1;
        }
    }

    // q_pe rope in place (deinterleave) — each warp owns one head per iteration
    for (int p = threadIdx.x; p < NH_ * 32; p += 128) {
        const int h = p >> 5, j = p & 31;
        const float c = cr[j], sn = sr[j];
        __half* qs = q16 + (long)t * (NH_*QHD_) + h * QHD_ + NOPE_;
        const float e = __half2float(qs[2*j]), o = __half2float(qs[2*j + 1]);
        __syncwarp();
        qs[j]      = __float2half_rn(e * c - o * sn);
        qs[32 + j] = __float2half_rn(o * c + e * sn);
    }
}

// ---------------- causal softmax: 1-pass smem-cached, fp16 probs ----------------
__global__ __launch_bounds__(256)
void softmax_causal(const float* __restrict__ sc, __half* __restrict__ pr)
{
    const float scale = 0.07216878364870322f;   // 192^-0.5
    __shared__ float buf[S_];
    __shared__ float red[8];
    const long row = blockIdx.x;
    const int qi = (int)(row & (S_ - 1));
    const float* p = sc + row * (long)S_;
    __half* o = pr + row * (long)S_;
    const int n = qi + 1;
    const int nend = ((qi >> 7) + 1) << 7;

    const int lane = threadIdx.x & 31, wid = threadIdx.x >> 5;

    float m = -1e30f;
    for (int k = threadIdx.x; k < n; k += 256) { float v = p[k]; buf[k] = v; m = fmaxf(m, v); }
#pragma unroll
    for (int off = 16; off; off >>= 1) m = fmaxf(m, __shfl_xor_sync(0xffffffffu, m, off));
    if (lane == 0) red[wid] = m;
    __syncthreads();
    if (threadIdx.x == 0) {
        float mm = red[0];
#pragma unroll
        for (int i = 1; i < 8; i++) mm = fmaxf(mm, red[i]);
        red[0] = mm;
    }
    __syncthreads();
    const float M = red[0] * scale;
    __syncthreads();

    float sum = 0.f;
    for (int k = threadIdx.x; k < n; k += 256) {
        float e = __expf(buf[k] * scale - M);
        buf[k] = e;
        sum += e;
    }
#pragma unroll
    for (int off = 16; off; off >>= 1) sum += __shfl_xor_sync(0xffffffffu, sum, off);
    if (lane == 0) red[wid] = sum;
    __syncthreads();
    if (threadIdx.x == 0) {
        float t = 0.f;
#pragma unroll
        for (int i = 0; i < 8; i++) t += red[i];
        red[0] = 1.0f / t;
    }
    __syncthreads();
    const float invs = red[0];

    for (int k = threadIdx.x; k < n; k += 256)
        o[k] = __float2half_rn(buf[k] * invs);
    for (int k = n + threadIdx.x; k < nend; k += 256)
        o[k] = __float2half_rn(0.f);
}

// ---------------- host ----------------
template<typename CT>
static void hgemm_t(const __half* A, const __half* B, CT* C,
                    int M, int N, int K, int lda, int ldb, int ldc, int Z, int zdiv,
                    long aO, long aI, long bO, long bI, long cO, long cI, int cmode)
{
    if (N % 128 == 0) {
        int sm = 3 * 128 * PAD_ * 2 * 2;                    // 61440
        cudaFuncSetAttribute(hgemm_mma<128, CT>, cudaFuncAttributeMaxDynamicSharedMemorySize, sm);
        dim3 g(N / 128, M / 128, Z);
        hgemm_mma<128, CT><<<g, 256, sm>>>(A, B, C, K, lda, ldb, ldc, zdiv, aO, aI, bO, bI, cO, cI, cmode);
    } else {
        int sm = 3 * 128 * PAD_ * 2 + 3 * 64 * PAD_ * 2;    // 46080
        cudaFuncSetAttribute(hgemm_mma<64, CT>, cudaFuncAttributeMaxDynamicSharedMemorySize, sm);
        dim3 g(N / 64, M / 128, Z);
        hgemm_mma<64, CT><<<g, 256, sm>>>(A, B, C, K, lda, ldb, ldc, zdiv, aO, aI, bO, bI, cO, cI, cmode);
    }
}

static void cvt(const float* in, __half* out, long n)
{
    long n4 = n / 4;
    int blocks = (int)((n4 + 255) / 256); if (blocks > 8192) blocks = 8192;
    f32tof16<<<blocks, 256>>>(in, out, n4);
}

extern "C" void kernel_launch(void* const* d_in, const int* in_sizes, int n_in,
                              void* d_out, int out_size)
{
    const float* hs    = (const float*)d_in[0];
    const int*   pos   = (const int*)d_in[2];
    const float* cosc  = (const float*)d_in[3];
    const float* sinc  = (const float*)d_in[4];
    const float* Wq    = (const float*)d_in[5];
    const float* Wkv_a = (const float*)d_in[6];
    const float* lnw   = (const float*)d_in[7];
    const float* Wkv_b = (const float*)d_in[8];
    const float* Wo    = (const float*)d_in[9];
    float* out = (float*)d_out;

    float* scores;
    cudaGetSymbolAddress((void**)&scores, g_scores);

    __half *hs16, *WqT, *WkvaT, *WoT, *Wkvb16, *q16, *ckvraw16, *ckv16, *keff16, *ckvT, *probs16, *x16, *attn16;
    cudaGetSymbolAddress((void**)&hs16, g_hs16);
    cudaGetSymbolAddress((void**)&WqT, g_WqT16);
    cudaGetSymbolAddress((void**)&WkvaT, g_WkvaT16);
    cudaGetSymbolAddress((void**)&WoT, g_WoT16);
    cudaGetSymbolAddress((void**)&Wkvb16, g_Wkvb16);
    cudaGetSymbolAddress((void**)&q16, g_q16);
    cudaGetSymbolAddress((void**)&ckvraw16, g_ckvraw16);
    cudaGetSymbolAddress((void**)&ckv16, g_ckv16);
    cudaGetSymbolAddress((void**)&keff16, g_keff16);
    cudaGetSymbolAddress((void**)&ckvT, g_ckvT16);
    cudaGetSymbolAddress((void**)&probs16, g_probs16);
    cudaGetSymbolAddress((void**)&x16, g_x16);
    cudaGetSymbolAddress((void**)&attn16, g_attn16);

    // ---- prep: fp16 inputs + K-major projection weights ----
    cvt(hs, hs16, (long)NTOK_ * H_);
    cvt(Wkv_b, Wkvb16, (long)NH_ * 256 * RANK_);
    transp_f32f16<<<dim3((NH_*QHD_)/32, H_/32, 1), 256>>>(Wq, WqT, NH_*QHD_, H_, 0, 0);
    transp_f32f16<<<dim3(DATT_/32, H_/32, 1), 256>>>(Wkv_a, WkvaT, DATT_, H_, 0, 0);
    transp_f32f16<<<dim3(H_/32, H_/32, 1), 256>>>(Wo, WoT, H_, H_, 0, 0);

    // 1) q16 = hs @ Wq  (fp16)
    hgemm_t<__half>(hs16, WqT, q16, NTOK_, NH_*QHD_, H_, H_, H_, NH_*QHD_, 1, 1, 0,0,0,0,0,0, 0);
    // 2) ckvraw16 = hs @ Wkv_a  (fp16)
    hgemm_t<__half>(hs16, WkvaT, ckvraw16, NTOK_, DATT_, H_, H_, H_, DATT_, 1, 1, 0,0,0,0,0,0, 0);

    // 3) rms + rope: ckv16, keff k_pe cols, q16 roped in place
    rmsrope_kernel<<<NTOK_, 128>>>(q16, ckvraw16, pos, cosc, sinc, lnw, ckv16, keff16);

    // 4) Keff[b,h] = ckv16[b] @ q_absorb[h]^T  -> keff cols 0..127
    hgemm_t<__half>(ckv16, Wkvb16, keff16, S_, NOPE_, RANK_, RANK_, RANK_, QHD_,
          B_*NH_, NH_,
          (long)S_*RANK_, 0,
          0, (long)256*RANK_,
          (long)NH_*S_*QHD_, (long)S_*QHD_, 0);

    // 5) ckv^T per batch (for PV)
    transp_f16<<<dim3(RANK_/32, S_/32, B_), 256>>>(ckv16, ckvT, RANK_, S_,
                                                   (long)S_*RANK_, (long)RANK_*S_);

    // 6) scores = q16[b,:,h] @ keff[b,h]^T   (K=192, causal skip)
    hgemm_t<float>(q16, keff16, scores, S_, S_, QHD_, NH_*QHD_, QHD_, S_,
          B_*NH_, NH_,
          (long)S_*(NH_*QHD_), (long)QHD_,
          (long)NH_*S_*QHD_, (long)S_*QHD_,
          (long)NH_*S_*S_, (long)S_*S_, 1);

    // 7) softmax -> fp16 probs
    softmax_causal<<<B_*NH_*S_, 256>>>(scores, probs16);

    // 8) x = probs @ ckv  (K clamped causal)
    hgemm_t<__half>(probs16, ckvT, x16, S_, RANK_, S_, S_, S_, RANK_,
          B_*NH_, NH_,
          (long)NH_*S_*S_, (long)S_*S_,
          (long)RANK_*S_, 0,
          (long)NH_*S_*RANK_, (long)S_*RANK_, 2);

    // 9) attn = x @ out_absorb^T   (out_absorb = Wkv_b[h,128:256,:], natural layout)
    hgemm_t<__half>(x16, Wkvb16 + (long)NOPE_*RANK_, attn16, S_, VDIM_, RANK_, RANK_, RANK_, NH_*VDIM_,
          B_*NH_, NH_,
          (long)NH_*S_*RANK_, (long)S_*RANK_,
          0, (long)256*RANK_,
          (long)S_*(NH_*VDIM_), (long)VDIM_, 0);

    // 10) out = attn @ Wo  (fp32 final)
    hgemm_t<float>(attn16, WoT, out, NTOK_, H_, NH_*VDIM_, NH_*VDIM_, NH_*VDIM_, H_, 1, 1, 0,0,0,0,0,0, 0);
}

// round 6
// speedup vs baseline: 12.4508x; 1.0850x over previous
#include <cuda_runtime.h>
#include <cuda_fp16.h>
#include <math.h>
#include <stdint.h>

// Problem constants
#define B_    2
#define S_    2048
#define H_    2048
#define NH_   16
#define NOPE_ 128
#define ROPE_ 64
#define VDIM_ 128
#define RANK_ 512
#define QHD_  192
#define DATT_ 576
#define NTOK_ (B_*S_)

// ---------------- scratch ----------------
__device__ float g_scores[(long)B_*NH_*S_ * S_];

__device__ unsigned short g_hs16[(long)NTOK_ * H_];
__device__ unsigned short g_WqT16[(long)(NH_*QHD_) * H_];
__device__ unsigned short g_WkvaT16[(long)DATT_ * H_];
__device__ unsigned short g_WoT16[(long)H_ * (NH_*VDIM_)];
__device__ unsigned short g_Wkvb16[(long)NH_ * 256 * RANK_];
__device__ unsigned short g_q16[(long)NTOK_ * (NH_*QHD_)];       // roped in place
__device__ unsigned short g_ckvraw16[(long)NTOK_ * DATT_];
__device__ unsigned short g_ckv16[(long)NTOK_ * RANK_];          // rms-normed
__device__ unsigned short g_keff16[(long)B_*NH_*S_ * QHD_];      // [ckv@qabs^T | k_pe]
__device__ unsigned short g_ckvT16[(long)B_ * RANK_ * S_];
__device__ unsigned short g_probs16[(long)B_*NH_*S_ * S_];
__device__ unsigned short g_x16[(long)B_*NH_*S_ * RANK_];
__device__ unsigned short g_attn16[(long)NTOK_ * (NH_*VDIM_)];

// ---------------- helpers ----------------
__device__ __forceinline__ uint32_t su32(const void* p){ return (uint32_t)__cvta_generic_to_shared((void*)p); }

#define CP_ASYNC16(dst, src) asm volatile("cp.async.cg.shared.global [%0], [%1], 16;" :: "r"(dst), "l"(src))
#define CP_COMMIT()          asm volatile("cp.async.commit_group;" ::: "memory")
#define CP_WAIT(n)           asm volatile("cp.async.wait_group %0;" :: "n"(n) : "memory")

__device__ __forceinline__ void ldmx4(uint32_t& r0, uint32_t& r1, uint32_t& r2, uint32_t& r3, uint32_t addr){
    asm volatile("ldmatrix.sync.aligned.m8n8.x4.shared.b16 {%0,%1,%2,%3}, [%4];"
                 : "=r"(r0), "=r"(r1), "=r"(r2), "=r"(r3) : "r"(addr));
}
__device__ __forceinline__ void mma16816(float* c, const uint32_t* a, const uint32_t* b){
    asm volatile("mma.sync.aligned.m16n8k16.row.col.f32.f16.f16.f32 "
                 "{%0,%1,%2,%3}, {%4,%5,%6,%7}, {%8,%9}, {%0,%1,%2,%3};"
                 : "+f"(c[0]), "+f"(c[1]), "+f"(c[2]), "+f"(c[3])
                 : "r"(a[0]), "r"(a[1]), "r"(a[2]), "r"(a[3]), "r"(b[0]), "r"(b[1]));
}

// ---------------- HMMA NT GEMM: C = A(f16,MxK) @ B(f16,NxK)^T ----------------
// CTA tile 128 x BN, K-tile 64, 256 threads (8 warps = 4M x 2N), 3-stage cp.async,
// one __syncthreads per 64-K iteration.
// cmode: 0 = plain, 1 = skip CTA when bn >= bm+128 (causal upper), 2 = clamp K to bm+128.
#define KT_   64
#define PAD_  72     // halfs per smem row (144B stride, ldmatrix conflict-free)

template<int BN, typename CT>
__global__ __launch_bounds__(256, 2)
void hgemm_mma(const __half* __restrict__ A, const __half* __restrict__ B, CT* __restrict__ C,
               int K, int lda, int ldb, int ldc,
               int zdiv, long aOut, long aIn, long bOut, long bIn, long cOut, long cIn,
               int cmode)
{
    constexpr int NT = BN / 16;
    constexpr int ASTR = 128 * PAD_ * 2;
    constexpr int BSTR = BN * PAD_ * 2;
    extern __shared__ char smem[];
    const uint32_t saBase = su32(smem);
    const uint32_t sbBase = saBase + 3 * ASTR;

    const int bm = blockIdx.y * 128;
    const int bn = blockIdx.x * BN;
    if (cmode == 1 && bn >= bm + 128) return;

    const int z = blockIdx.z;
    A += (long)(z / zdiv) * aOut + (long)(z % zdiv) * aIn;
    B += (long)(z / zdiv) * bOut + (long)(z % zdiv) * bIn;
    C += (long)(z / zdiv) * cOut + (long)(z % zdiv) * cIn;

    const int Keff = (cmode == 2) ? min(K, bm + 128) : K;
    const int NC = Keff / KT_;

    const int tid = threadIdx.x;
    const int lane = tid & 31, wp = tid >> 5;
    const int mw = wp >> 1;
    const int nw = wp & 1;
    constexpr int WN = BN / 2;

    const int arow = mw * 32 + (lane & 15);
    const int acol = (lane >> 4) * 8;
    const int brow = nw * WN + (lane & 7) + ((lane >> 4) << 3);
    const int bcol = ((lane >> 3) & 1) * 8;

    auto load_async = [&](int kt, int s){
        uint32_t sa = saBase + s * ASTR;
#pragma unroll
        for (int i = 0; i < 4; i++) {                 // A: 128 rows x 8 chunks of 16B
            int v = tid + i * 256;
            int r = v >> 3, c8 = (v & 7) * 8;
            CP_ASYNC16(sa + (r * PAD_ + c8) * 2, A + (long)(bm + r) * lda + kt + c8);
        }
        uint32_t sb = sbBase + s * BSTR;
#pragma unroll
        for (int i = 0; i < BN / 32; i++) {           // B: BN rows x 8 chunks
            int v = tid + i * 256;
            int r = v >> 3, c8 = (v & 7) * 8;
            CP_ASYNC16(sb + (r * PAD_ + c8) * 2, B + (long)(bn + r) * ldb + kt + c8);
        }
    };

    float acc[2][NT][4];
#pragma unroll
    for (int mt = 0; mt < 2; mt++)
#pragma unroll
        for (int nt = 0; nt < NT; nt++)
#pragma unroll
            for (int i = 0; i < 4; i++) acc[mt][nt][i] = 0.f;

    load_async(0, 0);  CP_COMMIT();
    if (NC > 1) load_async(KT_, 1);
    CP_COMMIT();

    for (int c = 0; c < NC; c++) {
        if (c == NC - 1) { CP_WAIT(0); } else { CP_WAIT(1); }
        __syncthreads();
        if (c + 2 < NC) { load_async((c + 2) * KT_, (c + 2) % 3); CP_COMMIT(); }

        const int s = c - (c / 3) * 3;
        const uint32_t sa = saBase + s * ASTR;
        const uint32_t sb = sbBase + s * BSTR;

#pragma unroll
        for (int kk = 0; kk < KT_; kk += 16) {
            uint32_t afr[2][4];
#pragma unroll
            for (int mt = 0; mt < 2; mt++)
                ldmx4(afr[mt][0], afr[mt][1], afr[mt][2], afr[mt][3],
                      sa + (uint32_t)(((arow + mt * 16) * PAD_ + kk + acol) * 2));
            uint32_t bfr[NT][2];
#pragma unroll
            for (int p = 0; p < NT / 2; p++)
                ldmx4(bfr[2*p][0], bfr[2*p][1], bfr[2*p+1][0], bfr[2*p+1][1],
                      sb + (uint32_t)(((brow + p * 16) * PAD_ + kk + bcol) * 2));
#pragma unroll
            for (int mt = 0; mt < 2; mt++)
#pragma unroll
                for (int nt = 0; nt < NT; nt++)
                    mma16816(acc[mt][nt], afr[mt], bfr[nt]);
        }
    }

    // epilogue
    const int g = lane >> 2, tg = lane & 3;
#pragma unroll
    for (int mt = 0; mt < 2; mt++) {
        const int row = bm + mw * 32 + mt * 16 + g;
#pragma unroll
        for (int nt = 0; nt < NT; nt++) {
            const int col = bn + nw * WN + nt * 8 + tg * 2;
            if constexpr (sizeof(CT) == 2) {
                *reinterpret_cast<__half2*>((__half*)C + (long)row * ldc + col) =
                    __floats2half2_rn(acc[mt][nt][0], acc[mt][nt][1]);
                *reinterpret_cast<__half2*>((__half*)C + (long)(row + 8) * ldc + col) =
                    __floats2half2_rn(acc[mt][nt][2], acc[mt][nt][3]);
            } else {
                *reinterpret_cast<float2*>((float*)C + (long)row * ldc + col) =
                    make_float2(acc[mt][nt][0], acc[mt][nt][1]);
                *reinterpret_cast<float2*>((float*)C + (long)(row + 8) * ldc + col) =
                    make_float2(acc[mt][nt][2], acc[mt][nt][3]);
            }
        }
    }
}

// ---------------- converts ----------------
__global__ __launch_bounds__(256) void f32tof16(const float* __restrict__ in, __half* __restrict__ out, long n4)
{
    long i = blockIdx.x * 256L + threadIdx.x;
    long stride = (long)gridDim.x * 256;
    for (; i < n4; i += stride) {
        float4 v = reinterpret_cast<const float4*>(in)[i];
        reinterpret_cast<__half2*>(out)[2*i]   = __floats2half2_rn(v.x, v.y);
        reinterpret_cast<__half2*>(out)[2*i+1] = __floats2half2_rn(v.z, v.w);
    }
}

// out[c][r] = (half) in[r][c]   (f32 input)
__global__ __launch_bounds__(256) void transp_f32f16(const float* __restrict__ in, __half* __restrict__ out,
                                                     int ldin, int ldout, long inB, long outB)
{
    __shared__ float t[32][33];
    const int z = blockIdx.z;
    in += (long)z * inB; out += (long)z * outB;
    const int r0 = blockIdx.y * 32, c0 = blockIdx.x * 32;
    const int x = threadIdx.x & 31, y = threadIdx.x >> 5;
#pragma unroll
    for (int i = 0; i < 32; i += 8)
        t[y + i][x] = in[(long)(r0 + y + i) * ldin + c0 + x];
    __syncthreads();
#pragma unroll
    for (int i = 0; i < 32; i += 8)
        out[(long)(c0 + y + i) * ldout + r0 + x] = __float2half_rn(t[x][y + i]);
}

// out[c][r] = in[r][c]   (f16 -> f16)
__global__ __launch_bounds__(256) void transp_f16(const __half* __restrict__ in, __half* __restrict__ out,
                                                  int ldin, int ldout, long inB, long outB)
{
    __shared__ __half t[32][34];
    const int z = blockIdx.z;
    in += (long)z * inB; out += (long)z * outB;
    const int r0 = blockIdx.y * 32, c0 = blockIdx.x * 32;
    const int x = threadIdx.x & 31, y = threadIdx.x >> 5;
#pragma unroll
    for (int i = 0; i < 32; i += 8)
        t[y + i][x] = in[(long)(r0 + y + i) * ldin + c0 + x];
    __syncthreads();
#pragma unroll
    for (int i = 0; i < 32; i += 8)
        out[(long)(c0 + y + i) * ldout + r0 + x] = t[x][y + i];
}

// ---------------- rmsnorm + rope (all fp16 tensors) ----------------
__global__ __launch_bounds__(128)
void rmsrope_kernel(__half* __restrict__ q16, const __half* __restrict__ ckvraw,
                    const int* __restrict__ pos_ids, const float* __restrict__ cosc,
                    const float* __restrict__ sinc, const float* __restrict__ lnw,
                    __half* __restrict__ ckv16, __half* __restrict__ keff)
{
    const int t = blockIdx.x;
    const int b = t / S_, s = t - b * S_;
    const __half* cv = ckvraw + (long)t * DATT_;

    __shared__ float red[4];
    float ss = 0.f;
    for (int i = threadIdx.x; i < RANK_; i += 128) { float v = __half2float(cv[i]); ss += v * v; }
#pragma unroll
    for (int o = 16; o; o >>= 1) ss += __shfl_xor_sync(0xffffffffu, ss, o);
    if ((threadIdx.x & 31) == 0) red[threadIdx.x >> 5] = ss;
    __syncthreads();
    const float inv = rsqrtf((red[0] + red[1] + red[2] + red[3]) * (1.0f / RANK_) + 1e-6f);

    __half* kd = ckv16 + (long)t * RANK_;
    for (int i = threadIdx.x; i < RANK_; i += 128)
        kd[i] = __float2half_rn(__half2float(cv[i]) * inv * lnw[i]);

    const int pos = pos_ids[t];
    const float* cr = cosc + (long)pos * ROPE_;
    const float* sr = sinc + (long)pos * ROPE_;

    if (threadIdx.x < 32) {
        const int j = threadIdx.x;
        const float c = cr[j], sn = sr[j];
        const float e = __half2float(cv[RANK_ + 2*j]), o = __half2float(cv[RANK_ + 2*j + 1]);
        const __half r0 = __float2half_rn(e * c - o * sn);
        const __half r1 = __float2half_rn(o * c + e * sn);
#pragma unroll
        for (int h = 0; h < NH_; h++) {
            __half* kb = keff + ((long)(b * NH_ + h) * S_ + s) * QHD_ + NOPE_;
            kb[j] = r0; kb[32 + j] = r1;
        }
    }

    for (int p = threadIdx.x; p < NH_ * 32; p += 128) {
        const int h = p >> 5, j = p & 31;
        const float c = cr[j], sn = sr[j];
        __half* qs = q16 + (long)t * (NH_*QHD_) + h * QHD_ + NOPE_;
        const float e = __half2float(qs[2*j]), o = __half2float(qs[2*j + 1]);
        __syncwarp();
        qs[j]      = __float2half_rn(e * c - o * sn);
        qs[32 + j] = __float2half_rn(o * c + e * sn);
    }
}

// ---------------- causal softmax: 1-pass smem-cached, fp16 probs ----------------
__global__ __launch_bounds__(256)
void softmax_causal(const float* __restrict__ sc, __half* __restrict__ pr)
{
    const float scale = 0.07216878364870322f;   // 192^-0.5
    __shared__ float buf[S_];
    __shared__ float red[8];
    const long row = blockIdx.x;
    const int qi = (int)(row & (S_ - 1));
    const float* p = sc + row * (long)S_;
    __half* o = pr + row * (long)S_;
    const int n = qi + 1;
    const int nend = ((qi >> 7) + 1) << 7;

    const int lane = threadIdx.x & 31, wid = threadIdx.x >> 5;

    float m = -1e30f;
    for (int k = threadIdx.x; k < n; k += 256) { float v = p[k]; buf[k] = v; m = fmaxf(m, v); }
#pragma unroll
    for (int off = 16; off; off >>= 1) m = fmaxf(m, __shfl_xor_sync(0xffffffffu, m, off));
    if (lane == 0) red[wid] = m;
    __syncthreads();
    if (threadIdx.x == 0) {
        float mm = red[0];
#pragma unroll
        for (int i = 1; i < 8; i++) mm = fmaxf(mm, red[i]);
        red[0] = mm;
    }
    __syncthreads();
    const float M = red[0] * scale;
    __syncthreads();

    float sum = 0.f;
    for (int k = threadIdx.x; k < n; k += 256) {
        float e = __expf(buf[k] * scale - M);
        buf[k] = e;
        sum += e;
    }
#pragma unroll
    for (int off = 16; off; off >>= 1) sum += __shfl_xor_sync(0xffffffffu, sum, off);
    if (lane == 0) red[wid] = sum;
    __syncthreads();
    if (threadIdx.x == 0) {
        float t = 0.f;
#pragma unroll
        for (int i = 0; i < 8; i++) t += red[i];
        red[0] = 1.0f / t;
    }
    __syncthreads();
    const float invs = red[0];

    for (int k = threadIdx.x; k < n; k += 256)
        o[k] = __float2half_rn(buf[k] * invs);
    for (int k = n + threadIdx.x; k < nend; k += 256)
        o[k] = __float2half_rn(0.f);
}

// ---------------- host ----------------
template<typename CT>
static void hgemm_t(const __half* A, const __half* B, CT* C,
                    int M, int N, int K, int lda, int ldb, int ldc, int Z, int zdiv,
                    long aO, long aI, long bO, long bI, long cO, long cI, int cmode)
{
    if (N % 128 == 0) {
        int sm = 3 * (128 + 128) * PAD_ * 2;                // 110592
        cudaFuncSetAttribute(hgemm_mma<128, CT>, cudaFuncAttributeMaxDynamicSharedMemorySize, sm);
        dim3 g(N / 128, M / 128, Z);
        hgemm_mma<128, CT><<<g, 256, sm>>>(A, B, C, K, lda, ldb, ldc, zdiv, aO, aI, bO, bI, cO, cI, cmode);
    } else {
        int sm = 3 * (128 + 64) * PAD_ * 2;                 // 82944
        cudaFuncSetAttribute(hgemm_mma<64, CT>, cudaFuncAttributeMaxDynamicSharedMemorySize, sm);
        dim3 g(N / 64, M / 128, Z);
        hgemm_mma<64, CT><<<g, 256, sm>>>(A, B, C, K, lda, ldb, ldc, zdiv, aO, aI, bO, bI, cO, cI, cmode);
    }
}

static void cvt(const float* in, __half* out, long n)
{
    long n4 = n / 4;
    int blocks = (int)((n4 + 255) / 256); if (blocks > 8192) blocks = 8192;
    f32tof16<<<blocks, 256>>>(in, out, n4);
}

extern "C" void kernel_launch(void* const* d_in, const int* in_sizes, int n_in,
                              void* d_out, int out_size)
{
    const float* hs    = (const float*)d_in[0];
    const int*   pos   = (const int*)d_in[2];
    const float* cosc  = (const float*)d_in[3];
    const float* sinc  = (const float*)d_in[4];
    const float* Wq    = (const float*)d_in[5];
    const float* Wkv_a = (const float*)d_in[6];
    const float* lnw   = (const float*)d_in[7];
    const float* Wkv_b = (const float*)d_in[8];
    const float* Wo    = (const float*)d_in[9];
    float* out = (float*)d_out;

    float* scores;
    cudaGetSymbolAddress((void**)&scores, g_scores);

    __half *hs16, *WqT, *WkvaT, *WoT, *Wkvb16, *q16, *ckvraw16, *ckv16, *keff16, *ckvT, *probs16, *x16, *attn16;
    cudaGetSymbolAddress((void**)&hs16, g_hs16);
    cudaGetSymbolAddress((void**)&WqT, g_WqT16);
    cudaGetSymbolAddress((void**)&WkvaT, g_WkvaT16);
    cudaGetSymbolAddress((void**)&WoT, g_WoT16);
    cudaGetSymbolAddress((void**)&Wkvb16, g_Wkvb16);
    cudaGetSymbolAddress((void**)&q16, g_q16);
    cudaGetSymbolAddress((void**)&ckvraw16, g_ckvraw16);
    cudaGetSymbolAddress((void**)&ckv16, g_ckv16);
    cudaGetSymbolAddress((void**)&keff16, g_keff16);
    cudaGetSymbolAddress((void**)&ckvT, g_ckvT16);
    cudaGetSymbolAddress((void**)&probs16, g_probs16);
    cudaGetSymbolAddress((void**)&x16, g_x16);
    cudaGetSymbolAddress((void**)&attn16, g_attn16);

    // ---- prep: fp16 inputs + K-major projection weights ----
    cvt(hs, hs16, (long)NTOK_ * H_);
    cvt(Wkv_b, Wkvb16, (long)NH_ * 256 * RANK_);
    transp_f32f16<<<dim3((NH_*QHD_)/32, H_/32, 1), 256>>>(Wq, WqT, NH_*QHD_, H_, 0, 0);
    transp_f32f16<<<dim3(DATT_/32, H_/32, 1), 256>>>(Wkv_a, WkvaT, DATT_, H_, 0, 0);
    transp_f32f16<<<dim3(H_/32, H_/32, 1), 256>>>(Wo, WoT, H_, H_, 0, 0);

    // 1) q16 = hs @ Wq
    hgemm_t<__half>(hs16, WqT, q16, NTOK_, NH_*QHD_, H_, H_, H_, NH_*QHD_, 1, 1, 0,0,0,0,0,0, 0);
    // 2) ckvraw16 = hs @ Wkv_a
    hgemm_t<__half>(hs16, WkvaT, ckvraw16, NTOK_, DATT_, H_, H_, H_, DATT_, 1, 1, 0,0,0,0,0,0, 0);

    // 3) rms + rope
    rmsrope_kernel<<<NTOK_, 128>>>(q16, ckvraw16, pos, cosc, sinc, lnw, ckv16, keff16);

    // 4) Keff[b,h] = ckv16[b] @ q_absorb[h]^T  -> keff cols 0..127
    hgemm_t<__half>(ckv16, Wkvb16, keff16, S_, NOPE_, RANK_, RANK_, RANK_, QHD_,
          B_*NH_, NH_,
          (long)S_*RANK_, 0,
          0, (long)256*RANK_,
          (long)NH_*S_*QHD_, (long)S_*QHD_, 0);

    // 5) ckv^T per batch (for PV)
    transp_f16<<<dim3(RANK_/32, S_/32, B_), 256>>>(ckv16, ckvT, RANK_, S_,
                                                   (long)S_*RANK_, (long)RANK_*S_);

    // 6) scores = q16[b,:,h] @ keff[b,h]^T   (K=192, causal skip)
    hgemm_t<float>(q16, keff16, scores, S_, S_, QHD_, NH_*QHD_, QHD_, S_,
          B_*NH_, NH_,
          (long)S_*(NH_*QHD_), (long)QHD_,
          (long)NH_*S_*QHD_, (long)S_*QHD_,
          (long)NH_*S_*S_, (long)S_*S_, 1);

    // 7) softmax -> fp16 probs
    softmax_causal<<<B_*NH_*S_, 256>>>(scores, probs16);

    // 8) x = probs @ ckv  (K clamped causal)
    hgemm_t<__half>(probs16, ckvT, x16, S_, RANK_, S_, S_, S_, RANK_,
          B_*NH_, NH_,
          (long)NH_*S_*S_, (long)S_*S_,
          (long)RANK_*S_, 0,
          (long)NH_*S_*RANK_, (long)S_*RANK_, 2);

    // 9) attn = x @ out_absorb^T
    hgemm_t<__half>(x16, Wkvb16 + (long)NOPE_*RANK_, attn16, S_, VDIM_, RANK_, RANK_, RANK_, NH_*VDIM_,
          B_*NH_, NH_,
          (long)NH_*S_*RANK_, (long)S_*RANK_,
          0, (long)256*RANK_,
          (long)S_*(NH_*VDIM_), (long)VDIM_, 0);

    // 10) out = attn @ Wo
    hgemm_t<float>(attn16, WoT, out, NTOK_, H_, NH_*VDIM_, NH_*VDIM_, NH_*VDIM_, H_, 1, 1, 0,0,0,0,0,0, 0);
}

// round 7
// speedup vs baseline: 14.8808x; 1.1952x over previous
#include <cuda_runtime.h>
#include <cuda_fp16.h>
#include <math.h>
#include <stdint.h>

// Problem constants
#define B_    2
#define S_    2048
#define H_    2048
#define NH_   16
#define NOPE_ 128
#define ROPE_ 64
#define VDIM_ 128
#define RANK_ 512
#define QHD_  192
#define DATT_ 576
#define NTOK_ (B_*S_)

// ---------------- scratch ----------------
__device__ float g_scores[(long)B_*NH_*S_ * S_];

__device__ unsigned short g_hs16[(long)NTOK_ * H_];
__device__ unsigned short g_WqT16[(long)(NH_*QHD_) * H_];
__device__ unsigned short g_WkvaT16[(long)DATT_ * H_];
__device__ unsigned short g_WoT16[(long)H_ * (NH_*VDIM_)];
__device__ unsigned short g_Wkvb16[(long)NH_ * 256 * RANK_];
__device__ unsigned short g_q16[(long)NTOK_ * (NH_*QHD_)];       // roped in place
__device__ unsigned short g_ckvraw16[(long)NTOK_ * DATT_];
__device__ unsigned short g_ckv16[(long)NTOK_ * RANK_];          // rms-normed
__device__ unsigned short g_keff16[(long)B_*NH_*S_ * QHD_];      // [ckv@qabs^T | k_pe]
__device__ unsigned short g_veffT16[(long)B_*NH_ * VDIM_ * S_];  // out_absorb @ ckv^T
__device__ unsigned short g_probs16[(long)B_*NH_*S_ * S_];
__device__ unsigned short g_attn16[(long)NTOK_ * (NH_*VDIM_)];

// ---------------- helpers ----------------
__device__ __forceinline__ uint32_t su32(const void* p){ return (uint32_t)__cvta_generic_to_shared((void*)p); }

#define CP_ASYNC16(dst, src) asm volatile("cp.async.cg.shared.global [%0], [%1], 16;" :: "r"(dst), "l"(src))
#define CP_COMMIT()          asm volatile("cp.async.commit_group;" ::: "memory")
#define CP_WAIT(n)           asm volatile("cp.async.wait_group %0;" :: "n"(n) : "memory")

__device__ __forceinline__ void ldmx4(uint32_t& r0, uint32_t& r1, uint32_t& r2, uint32_t& r3, uint32_t addr){
    asm volatile("ldmatrix.sync.aligned.m8n8.x4.shared.b16 {%0,%1,%2,%3}, [%4];"
                 : "=r"(r0), "=r"(r1), "=r"(r2), "=r"(r3) : "r"(addr));
}
__device__ __forceinline__ void mma16816(float* c, const uint32_t* a, const uint32_t* b){
    asm volatile("mma.sync.aligned.m16n8k16.row.col.f32.f16.f16.f32 "
                 "{%0,%1,%2,%3}, {%4,%5,%6,%7}, {%8,%9}, {%0,%1,%2,%3};"
                 : "+f"(c[0]), "+f"(c[1]), "+f"(c[2]), "+f"(c[3])
                 : "r"(a[0]), "r"(a[1]), "r"(a[2]), "r"(a[3]), "r"(b[0]), "r"(b[1]));
}

// ---------------- HMMA NT GEMM: C = A(f16,MxK) @ B(f16,NxK)^T ----------------
// CTA tile 128 x BN, K-tile 64, 256 threads (8 warps = 4M x 2N), 3-stage cp.async.
// cmode: 0 = plain, 1 = skip CTA when bn >= bm+128 (causal upper), 2 = clamp K to bm+128.
#define KT_   64
#define PAD_  72     // halfs per smem row (144B stride, ldmatrix conflict-free)

template<int BN, typename CT>
__global__ __launch_bounds__(256, 2)
void hgemm_mma(const __half* __restrict__ A, const __half* __restrict__ B, CT* __restrict__ C,
               int K, int lda, int ldb, int ldc,
               int zdiv, long aOut, long aIn, long bOut, long bIn, long cOut, long cIn,
               int cmode)
{
    constexpr int NT = BN / 16;
    constexpr int ASTR = 128 * PAD_ * 2;
    constexpr int BSTR = BN * PAD_ * 2;
    extern __shared__ char smem[];
    const uint32_t saBase = su32(smem);
    const uint32_t sbBase = saBase + 3 * ASTR;

    const int bm = blockIdx.y * 128;
    const int bn = blockIdx.x * BN;
    if (cmode == 1 && bn >= bm + 128) return;

    const int z = blockIdx.z;
    A += (long)(z / zdiv) * aOut + (long)(z % zdiv) * aIn;
    B += (long)(z / zdiv) * bOut + (long)(z % zdiv) * bIn;
    C += (long)(z / zdiv) * cOut + (long)(z % zdiv) * cIn;

    const int Keff = (cmode == 2) ? min(K, bm + 128) : K;
    const int NC = Keff / KT_;

    const int tid = threadIdx.x;
    const int lane = tid & 31, wp = tid >> 5;
    const int mw = wp >> 1;
    const int nw = wp & 1;
    constexpr int WN = BN / 2;

    const int arow = mw * 32 + (lane & 15);
    const int acol = (lane >> 4) * 8;
    const int brow = nw * WN + (lane & 7) + ((lane >> 4) << 3);
    const int bcol = ((lane >> 3) & 1) * 8;

    auto load_async = [&](int kt, int s){
        uint32_t sa = saBase + s * ASTR;
#pragma unroll
        for (int i = 0; i < 4; i++) {                 // A: 128 rows x 8 chunks of 16B
            int v = tid + i * 256;
            int r = v >> 3, c8 = (v & 7) * 8;
            CP_ASYNC16(sa + (r * PAD_ + c8) * 2, A + (long)(bm + r) * lda + kt + c8);
        }
        uint32_t sb = sbBase + s * BSTR;
#pragma unroll
        for (int i = 0; i < BN / 32; i++) {           // B: BN rows x 8 chunks
            int v = tid + i * 256;
            int r = v >> 3, c8 = (v & 7) * 8;
            CP_ASYNC16(sb + (r * PAD_ + c8) * 2, B + (long)(bn + r) * ldb + kt + c8);
        }
    };

    float acc[2][NT][4];
#pragma unroll
    for (int mt = 0; mt < 2; mt++)
#pragma unroll
        for (int nt = 0; nt < NT; nt++)
#pragma unroll
            for (int i = 0; i < 4; i++) acc[mt][nt][i] = 0.f;

    load_async(0, 0);  CP_COMMIT();
    if (NC > 1) load_async(KT_, 1);
    CP_COMMIT();

    for (int c = 0; c < NC; c++) {
        if (c == NC - 1) { CP_WAIT(0); } else { CP_WAIT(1); }
        __syncthreads();
        if (c + 2 < NC) { load_async((c + 2) * KT_, (c + 2) % 3); CP_COMMIT(); }

        const int s = c - (c / 3) * 3;
        const uint32_t sa = saBase + s * ASTR;
        const uint32_t sb = sbBase + s * BSTR;

#pragma unroll
        for (int kk = 0; kk < KT_; kk += 16) {
            uint32_t afr[2][4];
#pragma unroll
            for (int mt = 0; mt < 2; mt++)
                ldmx4(afr[mt][0], afr[mt][1], afr[mt][2], afr[mt][3],
                      sa + (uint32_t)(((arow + mt * 16) * PAD_ + kk + acol) * 2));
            uint32_t bfr[NT][2];
#pragma unroll
            for (int p = 0; p < NT / 2; p++)
                ldmx4(bfr[2*p][0], bfr[2*p][1], bfr[2*p+1][0], bfr[2*p+1][1],
                      sb + (uint32_t)(((brow + p * 16) * PAD_ + kk + bcol) * 2));
#pragma unroll
            for (int mt = 0; mt < 2; mt++)
#pragma unroll
                for (int nt = 0; nt < NT; nt++)
                    mma16816(acc[mt][nt], afr[mt], bfr[nt]);
        }
    }

    // epilogue
    const int g = lane >> 2, tg = lane & 3;
#pragma unroll
    for (int mt = 0; mt < 2; mt++) {
        const int row = bm + mw * 32 + mt * 16 + g;
#pragma unroll
        for (int nt = 0; nt < NT; nt++) {
            const int col = bn + nw * WN + nt * 8 + tg * 2;
            if constexpr (sizeof(CT) == 2) {
                *reinterpret_cast<__half2*>((__half*)C + (long)row * ldc + col) =
                    __floats2half2_rn(acc[mt][nt][0], acc[mt][nt][1]);
                *reinterpret_cast<__half2*>((__half*)C + (long)(row + 8) * ldc + col) =
                    __floats2half2_rn(acc[mt][nt][2], acc[mt][nt][3]);
            } else {
                *reinterpret_cast<float2*>((float*)C + (long)row * ldc + col) =
                    make_float2(acc[mt][nt][0], acc[mt][nt][1]);
                *reinterpret_cast<float2*>((float*)C + (long)(row + 8) * ldc + col) =
                    make_float2(acc[mt][nt][2], acc[mt][nt][3]);
            }
        }
    }
}

// ---------------- converts ----------------
__global__ __launch_bounds__(256) void f32tof16(const float* __restrict__ in, __half* __restrict__ out, long n4)
{
    long i = blockIdx.x * 256L + threadIdx.x;
    long stride = (long)gridDim.x * 256;
    for (; i < n4; i += stride) {
        float4 v = reinterpret_cast<const float4*>(in)[i];
        reinterpret_cast<__half2*>(out)[2*i]   = __floats2half2_rn(v.x, v.y);
        reinterpret_cast<__half2*>(out)[2*i+1] = __floats2half2_rn(v.z, v.w);
    }
}

// out[c][r] = (half) in[r][c]   (f32 input)
__global__ __launch_bounds__(256) void transp_f32f16(const float* __restrict__ in, __half* __restrict__ out,
                                                     int ldin, int ldout, long inB, long outB)
{
    __shared__ float t[32][33];
    const int z = blockIdx.z;
    in += (long)z * inB; out += (long)z * outB;
    const int r0 = blockIdx.y * 32, c0 = blockIdx.x * 32;
    const int x = threadIdx.x & 31, y = threadIdx.x >> 5;
#pragma unroll
    for (int i = 0; i < 32; i += 8)
        t[y + i][x] = in[(long)(r0 + y + i) * ldin + c0 + x];
    __syncthreads();
#pragma unroll
    for (int i = 0; i < 32; i += 8)
        out[(long)(c0 + y + i) * ldout + r0 + x] = __float2half_rn(t[x][y + i]);
}

// ---------------- rmsnorm + rope (all fp16 tensors) ----------------
__global__ __launch_bounds__(128)
void rmsrope_kernel(__half* __restrict__ q16, const __half* __restrict__ ckvraw,
                    const int* __restrict__ pos_ids, const float* __restrict__ cosc,
                    const float* __restrict__ sinc, const float* __restrict__ lnw,
                    __half* __restrict__ ckv16, __half* __restrict__ keff)
{
    const int t = blockIdx.x;
    const int b = t / S_, s = t - b * S_;
    const __half* cv = ckvraw + (long)t * DATT_;

    __shared__ float red[4];
    float ss = 0.f;
    for (int i = threadIdx.x; i < RANK_; i += 128) { float v = __half2float(cv[i]); ss += v * v; }
#pragma unroll
    for (int o = 16; o; o >>= 1) ss += __shfl_xor_sync(0xffffffffu, ss, o);
    if ((threadIdx.x & 31) == 0) red[threadIdx.x >> 5] = ss;
    __syncthreads();
    const float inv = rsqrtf((red[0] + red[1] + red[2] + red[3]) * (1.0f / RANK_) + 1e-6f);

    __half* kd = ckv16 + (long)t * RANK_;
    for (int i = threadIdx.x; i < RANK_; i += 128)
        kd[i] = __float2half_rn(__half2float(cv[i]) * inv * lnw[i]);

    const int pos = pos_ids[t];
    const float* cr = cosc + (long)pos * ROPE_;
    const float* sr = sinc + (long)pos * ROPE_;

    if (threadIdx.x < 32) {
        const int j = threadIdx.x;
        const float c = cr[j], sn = sr[j];
        const float e = __half2float(cv[RANK_ + 2*j]), o = __half2float(cv[RANK_ + 2*j + 1]);
        const __half r0 = __float2half_rn(e * c - o * sn);
        const __half r1 = __float2half_rn(o * c + e * sn);
#pragma unroll
        for (int h = 0; h < NH_; h++) {
            __half* kb = keff + ((long)(b * NH_ + h) * S_ + s) * QHD_ + NOPE_;
            kb[j] = r0; kb[32 + j] = r1;
        }
    }

    for (int p = threadIdx.x; p < NH_ * 32; p += 128) {
        const int h = p >> 5, j = p & 31;
        const float c = cr[j], sn = sr[j];
        __half* qs = q16 + (long)t * (NH_*QHD_) + h * QHD_ + NOPE_;
        const float e = __half2float(qs[2*j]), o = __half2float(qs[2*j + 1]);
        __syncwarp();
        qs[j]      = __float2half_rn(e * c - o * sn);
        qs[32 + j] = __float2half_rn(o * c + e * sn);
    }
}

// ---------------- causal softmax: 1-pass smem-cached, fp16 probs ----------------
__global__ __launch_bounds__(256)
void softmax_causal(const float* __restrict__ sc, __half* __restrict__ pr)
{
    const float scale = 0.07216878364870322f;   // 192^-0.5
    __shared__ float buf[S_];
    __shared__ float red[8];
    const long row = blockIdx.x;
    const int qi = (int)(row & (S_ - 1));
    const float* p = sc + row * (long)S_;
    __half* o = pr + row * (long)S_;
    const int n = qi + 1;
    const int nend = ((qi >> 7) + 1) << 7;

    const int lane = threadIdx.x & 31, wid = threadIdx.x >> 5;

    float m = -1e30f;
    for (int k = threadIdx.x; k < n; k += 256) { float v = p[k]; buf[k] = v; m = fmaxf(m, v); }
#pragma unroll
    for (int off = 16; off; off >>= 1) m = fmaxf(m, __shfl_xor_sync(0xffffffffu, m, off));
    if (lane == 0) red[wid] = m;
    __syncthreads();
    if (threadIdx.x == 0) {
        float mm = red[0];
#pragma unroll
        for (int i = 1; i < 8; i++) mm = fmaxf(mm, red[i]);
        red[0] = mm;
    }
    __syncthreads();
    const float M = red[0] * scale;
    __syncthreads();

    float sum = 0.f;
    for (int k = threadIdx.x; k < n; k += 256) {
        float e = __expf(buf[k] * scale - M);
        buf[k] = e;
        sum += e;
    }
#pragma unroll
    for (int off = 16; off; off >>= 1) sum += __shfl_xor_sync(0xffffffffu, sum, off);
    if (lane == 0) red[wid] = sum;
    __syncthreads();
    if (threadIdx.x == 0) {
        float t = 0.f;
#pragma unroll
        for (int i = 0; i < 8; i++) t += red[i];
        red[0] = 1.0f / t;
    }
    __syncthreads();
    const float invs = red[0];

    for (int k = threadIdx.x; k < n; k += 256)
        o[k] = __float2half_rn(buf[k] * invs);
    for (int k = n + threadIdx.x; k < nend; k += 256)
        o[k] = __float2half_rn(0.f);
}

// ---------------- host ----------------
template<typename CT>
static void hgemm_t(const __half* A, const __half* B, CT* C,
                    int M, int N, int K, int lda, int ldb, int ldc, int Z, int zdiv,
                    long aO, long aI, long bO, long bI, long cO, long cI, int cmode)
{
    if (N % 128 == 0) {
        int sm = 3 * (128 + 128) * PAD_ * 2;                // 110592
        cudaFuncSetAttribute(hgemm_mma<128, CT>, cudaFuncAttributeMaxDynamicSharedMemorySize, sm);
        dim3 g(N / 128, M / 128, Z);
        hgemm_mma<128, CT><<<g, 256, sm>>>(A, B, C, K, lda, ldb, ldc, zdiv, aO, aI, bO, bI, cO, cI, cmode);
    } else {
        int sm = 3 * (128 + 64) * PAD_ * 2;                 // 82944
        cudaFuncSetAttribute(hgemm_mma<64, CT>, cudaFuncAttributeMaxDynamicSharedMemorySize, sm);
        dim3 g(N / 64, M / 128, Z);
        hgemm_mma<64, CT><<<g, 256, sm>>>(A, B, C, K, lda, ldb, ldc, zdiv, aO, aI, bO, bI, cO, cI, cmode);
    }
}

static void cvt(const float* in, __half* out, long n)
{
    long n4 = n / 4;
    int blocks = (int)((n4 + 255) / 256); if (blocks > 8192) blocks = 8192;
    f32tof16<<<blocks, 256>>>(in, out, n4);
}

extern "C" void kernel_launch(void* const* d_in, const int* in_sizes, int n_in,
                              void* d_out, int out_size)
{
    const float* hs    = (const float*)d_in[0];
    const int*   pos   = (const int*)d_in[2];
    const float* cosc  = (const float*)d_in[3];
    const float* sinc  = (const float*)d_in[4];
    const float* Wq    = (const float*)d_in[5];
    const float* Wkv_a = (const float*)d_in[6];
    const float* lnw   = (const float*)d_in[7];
    const float* Wkv_b = (const float*)d_in[8];
    const float* Wo    = (const float*)d_in[9];
    float* out = (float*)d_out;

    float* scores;
    cudaGetSymbolAddress((void**)&scores, g_scores);

    __half *hs16, *WqT, *WkvaT, *WoT, *Wkvb16, *q16, *ckvraw16, *ckv16, *keff16, *veffT, *probs16, *attn16;
    cudaGetSymbolAddress((void**)&hs16, g_hs16);
    cudaGetSymbolAddress((void**)&WqT, g_WqT16);
    cudaGetSymbolAddress((void**)&WkvaT, g_WkvaT16);
    cudaGetSymbolAddress((void**)&WoT, g_WoT16);
    cudaGetSymbolAddress((void**)&Wkvb16, g_Wkvb16);
    cudaGetSymbolAddress((void**)&q16, g_q16);
    cudaGetSymbolAddress((void**)&ckvraw16, g_ckvraw16);
    cudaGetSymbolAddress((void**)&ckv16, g_ckv16);
    cudaGetSymbolAddress((void**)&keff16, g_keff16);
    cudaGetSymbolAddress((void**)&veffT, g_veffT16);
    cudaGetSymbolAddress((void**)&probs16, g_probs16);
    cudaGetSymbolAddress((void**)&attn16, g_attn16);

    // ---- prep: fp16 inputs + K-major projection weights ----
    cvt(hs, hs16, (long)NTOK_ * H_);
    cvt(Wkv_b, Wkvb16, (long)NH_ * 256 * RANK_);
    transp_f32f16<<<dim3((NH_*QHD_)/32, H_/32, 1), 256>>>(Wq, WqT, NH_*QHD_, H_, 0, 0);
    transp_f32f16<<<dim3(DATT_/32, H_/32, 1), 256>>>(Wkv_a, WkvaT, DATT_, H_, 0, 0);
    transp_f32f16<<<dim3(H_/32, H_/32, 1), 256>>>(Wo, WoT, H_, H_, 0, 0);

    // 1) q16 = hs @ Wq
    hgemm_t<__half>(hs16, WqT, q16, NTOK_, NH_*QHD_, H_, H_, H_, NH_*QHD_, 1, 1, 0,0,0,0,0,0, 0);
    // 2) ckvraw16 = hs @ Wkv_a
    hgemm_t<__half>(hs16, WkvaT, ckvraw16, NTOK_, DATT_, H_, H_, H_, DATT_, 1, 1, 0,0,0,0,0,0, 0);

    // 3) rms + rope
    rmsrope_kernel<<<NTOK_, 128>>>(q16, ckvraw16, pos, cosc, sinc, lnw, ckv16, keff16);

    // 4) Keff[b,h] = ckv16[b] @ q_absorb[h]^T  -> keff cols 0..127
    hgemm_t<__half>(ckv16, Wkvb16, keff16, S_, NOPE_, RANK_, RANK_, RANK_, QHD_,
          B_*NH_, NH_,
          (long)S_*RANK_, 0,
          0, (long)256*RANK_,
          (long)NH_*S_*QHD_, (long)S_*QHD_, 0);

    // 5) VeffT[b,h] = out_absorb[h] @ ckv16[b]^T   (128 x S per bh)
    hgemm_t<__half>(Wkvb16 + (long)NOPE_*RANK_, ckv16, veffT, VDIM_, S_, RANK_,
          RANK_, RANK_, S_,
          B_*NH_, NH_,
          0, (long)256*RANK_,
          (long)S_*RANK_, 0,
          (long)NH_*VDIM_*S_, (long)VDIM_*S_, 0);

    // 6) scores = q16[b,:,h] @ keff[b,h]^T   (K=192, causal skip)
    hgemm_t<float>(q16, keff16, scores, S_, S_, QHD_, NH_*QHD_, QHD_, S_,
          B_*NH_, NH_,
          (long)S_*(NH_*QHD_), (long)QHD_,
          (long)NH_*S_*QHD_, (long)S_*QHD_,
          (long)NH_*S_*S_, (long)S_*S_, 1);

    // 7) softmax -> fp16 probs
    softmax_causal<<<B_*NH_*S_, 256>>>(scores, probs16);

    // 8) attn[b,:,h,:] = probs[b,h] @ VeffT[b,h]^T   (N=128, K clamped causal)
    hgemm_t<__half>(probs16, veffT, attn16, S_, VDIM_, S_, S_, S_, NH_*VDIM_,
          B_*NH_, NH_,
          (long)NH_*S_*S_, (long)S_*S_,
          (long)NH_*VDIM_*S_, (long)VDIM_*S_,
          (long)S_*(NH_*VDIM_), (long)VDIM_, 2);

    // 9) out = attn @ Wo
    hgemm_t<float>(attn16, WoT, out, NTOK_, H_, NH_*VDIM_, NH_*VDIM_, NH_*VDIM_, H_, 1, 1, 0,0,0,0,0,0, 0);
}

// round 8
// speedup vs baseline: 18.7779x; 1.2619x over previous
#include <cuda_runtime.h>
#include <cuda_fp16.h>
#include <math.h>
#include <stdint.h>

// Problem constants
#define B_    2
#define S_    2048
#define H_    2048
#define NH_   16
#define NOPE_ 128
#define ROPE_ 64
#define VDIM_ 128
#define RANK_ 512
#define QHD_  192
#define DATT_ 576
#define NTOK_ (B_*S_)

// ---------------- scratch ----------------
__device__ unsigned short g_hs16[(long)NTOK_ * H_];
__device__ unsigned short g_WqT16[(long)(NH_*QHD_) * H_];
__device__ unsigned short g_WkvaT16[(long)DATT_ * H_];
__device__ unsigned short g_WoT16[(long)H_ * (NH_*VDIM_)];
__device__ unsigned short g_Wkvb16[(long)NH_ * 256 * RANK_];
__device__ unsigned short g_q16[(long)NTOK_ * (NH_*QHD_)];       // roped in place
__device__ unsigned short g_ckvraw16[(long)NTOK_ * DATT_];
__device__ unsigned short g_ckv16[(long)NTOK_ * RANK_];          // rms-normed
__device__ unsigned short g_keff16[(long)B_*NH_*S_ * QHD_];      // [ckv@qabs^T | k_pe]
__device__ unsigned short g_veffT16[(long)B_*NH_ * VDIM_ * S_];  // out_absorb @ ckv^T
__device__ unsigned short g_attn16[(long)NTOK_ * (NH_*VDIM_)];

// ---------------- helpers ----------------
__device__ __forceinline__ uint32_t su32(const void* p){ return (uint32_t)__cvta_generic_to_shared((void*)p); }

#define CP_ASYNC16(dst, src) asm volatile("cp.async.cg.shared.global [%0], [%1], 16;" :: "r"(dst), "l"(src))
#define CP_COMMIT()          asm volatile("cp.async.commit_group;" ::: "memory")
#define CP_WAIT(n)           asm volatile("cp.async.wait_group %0;" :: "n"(n) : "memory")

__device__ __forceinline__ void ldmx4(uint32_t& r0, uint32_t& r1, uint32_t& r2, uint32_t& r3, uint32_t addr){
    asm volatile("ldmatrix.sync.aligned.m8n8.x4.shared.b16 {%0,%1,%2,%3}, [%4];"
                 : "=r"(r0), "=r"(r1), "=r"(r2), "=r"(r3) : "r"(addr));
}
__device__ __forceinline__ void mma16816(float* c, const uint32_t* a, const uint32_t* b){
    asm volatile("mma.sync.aligned.m16n8k16.row.col.f32.f16.f16.f32 "
                 "{%0,%1,%2,%3}, {%4,%5,%6,%7}, {%8,%9}, {%0,%1,%2,%3};"
                 : "+f"(c[0]), "+f"(c[1]), "+f"(c[2]), "+f"(c[3])
                 : "r"(a[0]), "r"(a[1]), "r"(a[2]), "r"(a[3]), "r"(b[0]), "r"(b[1]));
}
__device__ __forceinline__ uint32_t packh2(float a, float b){
    __half2 h = __floats2half2_rn(a, b);
    return *reinterpret_cast<uint32_t*>(&h);
}

// ---------------- HMMA NT GEMM: C = A(f16,MxK) @ B(f16,NxK)^T ----------------
#define KT_   64
#define PAD_  72

template<int BN, typename CT>
__global__ __launch_bounds__(256, 2)
void hgemm_mma(const __half* __restrict__ A, const __half* __restrict__ B, CT* __restrict__ C,
               int K, int lda, int ldb, int ldc,
               int zdiv, long aOut, long aIn, long bOut, long bIn, long cOut, long cIn)
{
    constexpr int NT = BN / 16;
    constexpr int ASTR = 128 * PAD_ * 2;
    constexpr int BSTR = BN * PAD_ * 2;
    extern __shared__ char smem[];
    const uint32_t saBase = su32(smem);
    const uint32_t sbBase = saBase + 3 * ASTR;

    const int bm = blockIdx.y * 128;
    const int bn = blockIdx.x * BN;

    const int z = blockIdx.z;
    A += (long)(z / zdiv) * aOut + (long)(z % zdiv) * aIn;
    B += (long)(z / zdiv) * bOut + (long)(z % zdiv) * bIn;
    C += (long)(z / zdiv) * cOut + (long)(z % zdiv) * cIn;

    const int NC = K / KT_;

    const int tid = threadIdx.x;
    const int lane = tid & 31, wp = tid >> 5;
    const int mw = wp >> 1;
    const int nw = wp & 1;
    constexpr int WN = BN / 2;

    const int arow = mw * 32 + (lane & 15);
    const int acol = (lane >> 4) * 8;
    const int brow = nw * WN + (lane & 7) + ((lane >> 4) << 3);
    const int bcol = ((lane >> 3) & 1) * 8;

    auto load_async = [&](int kt, int s){
        uint32_t sa = saBase + s * ASTR;
#pragma unroll
        for (int i = 0; i < 4; i++) {
            int v = tid + i * 256;
            int r = v >> 3, c8 = (v & 7) * 8;
            CP_ASYNC16(sa + (r * PAD_ + c8) * 2, A + (long)(bm + r) * lda + kt + c8);
        }
        uint32_t sb = sbBase + s * BSTR;
#pragma unroll
        for (int i = 0; i < BN / 32; i++) {
            int v = tid + i * 256;
            int r = v >> 3, c8 = (v & 7) * 8;
            CP_ASYNC16(sb + (r * PAD_ + c8) * 2, B + (long)(bn + r) * ldb + kt + c8);
        }
    };

    float acc[2][NT][4];
#pragma unroll
    for (int mt = 0; mt < 2; mt++)
#pragma unroll
        for (int nt = 0; nt < NT; nt++)
#pragma unroll
            for (int i = 0; i < 4; i++) acc[mt][nt][i] = 0.f;

    load_async(0, 0);  CP_COMMIT();
    if (NC > 1) load_async(KT_, 1);
    CP_COMMIT();

    for (int c = 0; c < NC; c++) {
        if (c == NC - 1) { CP_WAIT(0); } else { CP_WAIT(1); }
        __syncthreads();
        if (c + 2 < NC) { load_async((c + 2) * KT_, (c + 2) % 3); CP_COMMIT(); }

        const int s = c - (c / 3) * 3;
        const uint32_t sa = saBase + s * ASTR;
        const uint32_t sb = sbBase + s * BSTR;

#pragma unroll
        for (int kk = 0; kk < KT_; kk += 16) {
            uint32_t afr[2][4];
#pragma unroll
            for (int mt = 0; mt < 2; mt++)
                ldmx4(afr[mt][0], afr[mt][1], afr[mt][2], afr[mt][3],
                      sa + (uint32_t)(((arow + mt * 16) * PAD_ + kk + acol) * 2));
            uint32_t bfr[NT][2];
#pragma unroll
            for (int p = 0; p < NT / 2; p++)
                ldmx4(bfr[2*p][0], bfr[2*p][1], bfr[2*p+1][0], bfr[2*p+1][1],
                      sb + (uint32_t)(((brow + p * 16) * PAD_ + kk + bcol) * 2));
#pragma unroll
            for (int mt = 0; mt < 2; mt++)
#pragma unroll
                for (int nt = 0; nt < NT; nt++)
                    mma16816(acc[mt][nt], afr[mt], bfr[nt]);
        }
    }

    const int g = lane >> 2, tg = lane & 3;
#pragma unroll
    for (int mt = 0; mt < 2; mt++) {
        const int row = bm + mw * 32 + mt * 16 + g;
#pragma unroll
        for (int nt = 0; nt < NT; nt++) {
            const int col = bn + nw * WN + nt * 8 + tg * 2;
            if constexpr (sizeof(CT) == 2) {
                *reinterpret_cast<__half2*>((__half*)C + (long)row * ldc + col) =
                    __floats2half2_rn(acc[mt][nt][0], acc[mt][nt][1]);
                *reinterpret_cast<__half2*>((__half*)C + (long)(row + 8) * ldc + col) =
                    __floats2half2_rn(acc[mt][nt][2], acc[mt][nt][3]);
            } else {
                *reinterpret_cast<float2*>((float*)C + (long)row * ldc + col) =
                    make_float2(acc[mt][nt][0], acc[mt][nt][1]);
                *reinterpret_cast<float2*>((float*)C + (long)(row + 8) * ldc + col) =
                    make_float2(acc[mt][nt][2], acc[mt][nt][3]);
            }
        }
    }
}

// ---------------- fused flash attention: scores + softmax + PV ----------------
// CTA = (i-block of 128 q rows, bh). 8 warps x 16 rows. Q resident in smem,
// K/V blocks double-buffered cp.async. Online softmax, O accumulated fp32.
#define FBLK  128
#define NBLK  (S_/FBLK)   // 16
#define PADQ  200         // 192 + 8 halfs (400B row stride -> ldsm conflict-free)
#define PADV  136         // 128 + 8 halfs (272B)

__global__ __launch_bounds__(256, 1)
void flash_kernel(const __half* __restrict__ q, const __half* __restrict__ keff,
                  const __half* __restrict__ veff, __half* __restrict__ attn)
{
    extern __shared__ char smem[];
    __half* sQ = (__half*)smem;                               // 128 x PADQ
    const uint32_t sQa = su32(sQ);
    const uint32_t sKa[2] = { sQa + 128*PADQ*2, sQa + 2*128*PADQ*2 };
    const uint32_t sVa[2] = { sQa + 3*128*PADQ*2, sQa + 3*128*PADQ*2 + 128*PADV*2 };

    const int z = blockIdx.z;                  // bh
    const int b = z >> 4, h = z & (NH_-1);
    const int iblk = (NBLK - 1) - blockIdx.x;  // heavy blocks first

    const int tid = threadIdx.x, lane = tid & 31, w = tid >> 5;
    const int g = lane >> 2, tg = lane & 3;
    const int m0r = w * 16;

    const __half* Qbase = q + (long)(b*S_ + iblk*FBLK) * (NH_*QHD_) + h*QHD_;
    const __half* Kbase = keff + (long)z * S_ * QHD_;
    const __half* Vbase = veff + (long)z * VDIM_ * S_;

    // Q load (group 0 together with K0/V0)
    for (int v = tid; v < 128*24; v += 256) {
        int r = v / 24, c = v % 24;
        CP_ASYNC16(sQa + (r*PADQ + c*8)*2, Qbase + (long)r*(NH_*QHD_) + c*8);
    }
    auto loadK = [&](int j, int s){
        const __half* kb = Kbase + (long)j*FBLK*QHD_;
        for (int v = tid; v < 128*24; v += 256) {
            int r = v / 24, c = v % 24;
            CP_ASYNC16(sKa[s] + (r*PADQ + c*8)*2, kb + (long)r*QHD_ + c*8);
        }
    };
    auto loadV = [&](int j, int s){
        const __half* vb = Vbase + j*FBLK;
        for (int v = tid; v < 128*16; v += 256) {
            int r = v >> 4, c = v & 15;
            CP_ASYNC16(sVa[s] + (r*PADV + c*8)*2, vb + (long)r*S_ + c*8);
        }
    };
    loadK(0, 0); loadV(0, 0); CP_COMMIT();

    float Oacc[16][4];
#pragma unroll
    for (int nt = 0; nt < 16; nt++)
#pragma unroll
        for (int i = 0; i < 4; i++) Oacc[nt][i] = 0.f;
    float m0 = -1e30f, m1 = -1e30f, l0 = 0.f, l1 = 0.f;
    const float scale = 0.07216878364870322f;   // 192^-0.5

    const int arow = lane & 15;
    const int acol = (lane >> 4) * 8;
    const int brow = (lane & 7) + ((lane >> 4) << 3);
    const int bcol = ((lane >> 3) & 1) * 8;

    for (int j = 0; j <= iblk; j++) {
        const int s = j & 1;
        if (j < iblk) { loadK(j+1, s^1); loadV(j+1, s^1); CP_COMMIT(); CP_WAIT(1); }
        else          { CP_WAIT(0); }
        __syncthreads();

        // ---- S = Q @ Keff_j^T  (16 x 128 per warp) ----
        float Sacc[16][4];
#pragma unroll
        for (int nt = 0; nt < 16; nt++)
#pragma unroll
            for (int i = 0; i < 4; i++) Sacc[nt][i] = 0.f;

#pragma unroll
        for (int kk = 0; kk < QHD_; kk += 16) {
            uint32_t afr[4];
            ldmx4(afr[0], afr[1], afr[2], afr[3],
                  sQa + (uint32_t)(((m0r + arow)*PADQ + kk + acol)*2));
            uint32_t bfr[16][2];
#pragma unroll
            for (int p = 0; p < 8; p++)
                ldmx4(bfr[2*p][0], bfr[2*p][1], bfr[2*p+1][0], bfr[2*p+1][1],
                      sKa[s] + (uint32_t)(((p*16 + brow)*PADQ + kk + bcol)*2));
#pragma unroll
            for (int nt = 0; nt < 16; nt++)
                mma16816(Sacc[nt], afr, bfr[nt]);
        }

        // ---- causal mask on diagonal block ----
        if (j == iblk) {
            const int r0 = m0r + g, r1 = r0 + 8;
#pragma unroll
            for (int nt = 0; nt < 16; nt++) {
                const int c0 = nt*8 + tg*2;
                if (c0     > r0) Sacc[nt][0] = -1e30f;
                if (c0 + 1 > r0) Sacc[nt][1] = -1e30f;
                if (c0     > r1) Sacc[nt][2] = -1e30f;
                if (c0 + 1 > r1) Sacc[nt][3] = -1e30f;
            }
        }

        // ---- online softmax stats ----
        float bm0 = -1e30f, bm1 = -1e30f;
#pragma unroll
        for (int nt = 0; nt < 16; nt++) {
            bm0 = fmaxf(bm0, fmaxf(Sacc[nt][0], Sacc[nt][1]));
            bm1 = fmaxf(bm1, fmaxf(Sacc[nt][2], Sacc[nt][3]));
        }
        bm0 = fmaxf(bm0, __shfl_xor_sync(0xffffffffu, bm0, 1));
        bm0 = fmaxf(bm0, __shfl_xor_sync(0xffffffffu, bm0, 2));
        bm1 = fmaxf(bm1, __shfl_xor_sync(0xffffffffu, bm1, 1));
        bm1 = fmaxf(bm1, __shfl_xor_sync(0xffffffffu, bm1, 2));
        const float mn0 = fmaxf(m0, bm0), mn1 = fmaxf(m1, bm1);
        const float corr0 = __expf((m0 - mn0) * scale);
        const float corr1 = __expf((m1 - mn1) * scale);
        m0 = mn0; m1 = mn1;
        l0 *= corr0; l1 *= corr1;
#pragma unroll
        for (int nt = 0; nt < 16; nt++) {
            Oacc[nt][0] *= corr0; Oacc[nt][1] *= corr0;
            Oacc[nt][2] *= corr1; Oacc[nt][3] *= corr1;
        }

        // ---- P = exp((S-m)*scale) packed as A-frags; O += P @ Veff_j ----
#pragma unroll
        for (int t = 0; t < 8; t++) {
            const float e00 = __expf((Sacc[2*t  ][0] - m0) * scale);
            const float e01 = __expf((Sacc[2*t  ][1] - m0) * scale);
            const float e02 = __expf((Sacc[2*t  ][2] - m1) * scale);
            const float e03 = __expf((Sacc[2*t  ][3] - m1) * scale);
            const float e10 = __expf((Sacc[2*t+1][0] - m0) * scale);
            const float e11 = __expf((Sacc[2*t+1][1] - m0) * scale);
            const float e12 = __expf((Sacc[2*t+1][2] - m1) * scale);
            const float e13 = __expf((Sacc[2*t+1][3] - m1) * scale);
            l0 += e00 + e01 + e10 + e11;
            l1 += e02 + e03 + e12 + e13;
            uint32_t pa[4];
            pa[0] = packh2(e00, e01);
            pa[1] = packh2(e02, e03);
            pa[2] = packh2(e10, e11);
            pa[3] = packh2(e12, e13);
            uint32_t bfr[16][2];
#pragma unroll
            for (int p = 0; p < 8; p++)
                ldmx4(bfr[2*p][0], bfr[2*p][1], bfr[2*p+1][0], bfr[2*p+1][1],
                      sVa[s] + (uint32_t)(((p*16 + brow)*PADV + t*16 + bcol)*2));
#pragma unroll
            for (int nt = 0; nt < 16; nt++)
                mma16816(Oacc[nt], pa, bfr[nt]);
        }
        __syncthreads();
    }

    // ---- finalize: O /= l, write fp16 ----
    l0 += __shfl_xor_sync(0xffffffffu, l0, 1);
    l0 += __shfl_xor_sync(0xffffffffu, l0, 2);
    l1 += __shfl_xor_sync(0xffffffffu, l1, 1);
    l1 += __shfl_xor_sync(0xffffffffu, l1, 2);
    const float inv0 = 1.0f / l0, inv1 = 1.0f / l1;

    const long s0 = (long)(b*S_ + iblk*FBLK + m0r + g);
    __half* o0 = attn + (s0 * NH_ + h) * VDIM_;
    __half* o1 = attn + ((s0 + 8) * NH_ + h) * VDIM_;
#pragma unroll
    for (int nt = 0; nt < 16; nt++) {
        const int col = nt*8 + tg*2;
        *reinterpret_cast<__half2*>(o0 + col) = __floats2half2_rn(Oacc[nt][0]*inv0, Oacc[nt][1]*inv0);
        *reinterpret_cast<__half2*>(o1 + col) = __floats2half2_rn(Oacc[nt][2]*inv1, Oacc[nt][3]*inv1);
    }
}

// ---------------- converts ----------------
__global__ __launch_bounds__(256) void f32tof16(const float* __restrict__ in, __half* __restrict__ out, long n4)
{
    long i = blockIdx.x * 256L + threadIdx.x;
    long stride = (long)gridDim.x * 256;
    for (; i < n4; i += stride) {
        float4 v = reinterpret_cast<const float4*>(in)[i];
        reinterpret_cast<__half2*>(out)[2*i]   = __floats2half2_rn(v.x, v.y);
        reinterpret_cast<__half2*>(out)[2*i+1] = __floats2half2_rn(v.z, v.w);
    }
}

__global__ __launch_bounds__(256) void transp_f32f16(const float* __restrict__ in, __half* __restrict__ out,
                                                     int ldin, int ldout, long inB, long outB)
{
    __shared__ float t[32][33];
    const int z = blockIdx.z;
    in += (long)z * inB; out += (long)z * outB;
    const int r0 = blockIdx.y * 32, c0 = blockIdx.x * 32;
    const int x = threadIdx.x & 31, y = threadIdx.x >> 5;
#pragma unroll
    for (int i = 0; i < 32; i += 8)
        t[y + i][x] = in[(long)(r0 + y + i) * ldin + c0 + x];
    __syncthreads();
#pragma unroll
    for (int i = 0; i < 32; i += 8)
        out[(long)(c0 + y + i) * ldout + r0 + x] = __float2half_rn(t[x][y + i]);
}

// ---------------- rmsnorm + rope (all fp16 tensors) ----------------
__global__ __launch_bounds__(128)
void rmsrope_kernel(__half* __restrict__ q16, const __half* __restrict__ ckvraw,
                    const int* __restrict__ pos_ids, const float* __restrict__ cosc,
                    const float* __restrict__ sinc, const float* __restrict__ lnw,
                    __half* __restrict__ ckv16, __half* __restrict__ keff)
{
    const int t = blockIdx.x;
    const int b = t / S_, s = t - b * S_;
    const __half* cv = ckvraw + (long)t * DATT_;

    __shared__ float red[4];
    float ss = 0.f;
    for (int i = threadIdx.x; i < RANK_; i += 128) { float v = __half2float(cv[i]); ss += v * v; }
#pragma unroll
    for (int o = 16; o; o >>= 1) ss += __shfl_xor_sync(0xffffffffu, ss, o);
    if ((threadIdx.x & 31) == 0) red[threadIdx.x >> 5] = ss;
    __syncthreads();
    const float inv = rsqrtf((red[0] + red[1] + red[2] + red[3]) * (1.0f / RANK_) + 1e-6f);

    __half* kd = ckv16 + (long)t * RANK_;
    for (int i = threadIdx.x; i < RANK_; i += 128)
        kd[i] = __float2half_rn(__half2float(cv[i]) * inv * lnw[i]);

    const int pos = pos_ids[t];
    const float* cr = cosc + (long)pos * ROPE_;
    const float* sr = sinc + (long)pos * ROPE_;

    if (threadIdx.x < 32) {
        const int j = threadIdx.x;
        const float c = cr[j], sn = sr[j];
        const float e = __half2float(cv[RANK_ + 2*j]), o = __half2float(cv[RANK_ + 2*j + 1]);
        const __half r0 = __float2half_rn(e * c - o * sn);
        const __half r1 = __float2half_rn(o * c + e * sn);
#pragma unroll
        for (int h = 0; h < NH_; h++) {
            __half* kb = keff + ((long)(b * NH_ + h) * S_ + s) * QHD_ + NOPE_;
            kb[j] = r0; kb[32 + j] = r1;
        }
    }

    for (int p = threadIdx.x; p < NH_ * 32; p += 128) {
        const int h = p >> 5, j = p & 31;
        const float c = cr[j], sn = sr[j];
        __half* qs = q16 + (long)t * (NH_*QHD_) + h * QHD_ + NOPE_;
        const float e = __half2float(qs[2*j]), o = __half2float(qs[2*j + 1]);
        __syncwarp();
        qs[j]      = __float2half_rn(e * c - o * sn);
        qs[32 + j] = __float2half_rn(o * c + e * sn);
    }
}

// ---------------- host ----------------
template<typename CT>
static void hgemm_t(const __half* A, const __half* B, CT* C,
                    int M, int N, int K, int lda, int ldb, int ldc, int Z, int zdiv,
                    long aO, long aI, long bO, long bI, long cO, long cI)
{
    if (N % 128 == 0) {
        int sm = 3 * (128 + 128) * PAD_ * 2;
        cudaFuncSetAttribute(hgemm_mma<128, CT>, cudaFuncAttributeMaxDynamicSharedMemorySize, sm);
        dim3 g(N / 128, M / 128, Z);
        hgemm_mma<128, CT><<<g, 256, sm>>>(A, B, C, K, lda, ldb, ldc, zdiv, aO, aI, bO, bI, cO, cI);
    } else {
        int sm = 3 * (128 + 64) * PAD_ * 2;
        cudaFuncSetAttribute(hgemm_mma<64, CT>, cudaFuncAttributeMaxDynamicSharedMemorySize, sm);
        dim3 g(N / 64, M / 128, Z);
        hgemm_mma<64, CT><<<g, 256, sm>>>(A, B, C, K, lda, ldb, ldc, zdiv, aO, aI, bO, bI, cO, cI);
    }
}

static void cvt(const float* in, __half* out, long n)
{
    long n4 = n / 4;
    int blocks = (int)((n4 + 255) / 256); if (blocks > 8192) blocks = 8192;
    f32tof16<<<blocks, 256>>>(in, out, n4);
}

extern "C" void kernel_launch(void* const* d_in, const int* in_sizes, int n_in,
                              void* d_out, int out_size)
{
    const float* hs    = (const float*)d_in[0];
    const int*   pos   = (const int*)d_in[2];
    const float* cosc  = (const float*)d_in[3];
    const float* sinc  = (const float*)d_in[4];
    const float* Wq    = (const float*)d_in[5];
    const float* Wkv_a = (const float*)d_in[6];
    const float* lnw   = (const float*)d_in[7];
    const float* Wkv_b = (const float*)d_in[8];
    const float* Wo    = (const float*)d_in[9];
    float* out = (float*)d_out;

    __half *hs16, *WqT, *WkvaT, *WoT, *Wkvb16, *q16, *ckvraw16, *ckv16, *keff16, *veffT, *attn16;
    cudaGetSymbolAddress((void**)&hs16, g_hs16);
    cudaGetSymbolAddress((void**)&WqT, g_WqT16);
    cudaGetSymbolAddress((void**)&WkvaT, g_WkvaT16);
    cudaGetSymbolAddress((void**)&WoT, g_WoT16);
    cudaGetSymbolAddress((void**)&Wkvb16, g_Wkvb16);
    cudaGetSymbolAddress((void**)&q16, g_q16);
    cudaGetSymbolAddress((void**)&ckvraw16, g_ckvraw16);
    cudaGetSymbolAddress((void**)&ckv16, g_ckv16);
    cudaGetSymbolAddress((void**)&keff16, g_keff16);
    cudaGetSymbolAddress((void**)&veffT, g_veffT16);
    cudaGetSymbolAddress((void**)&attn16, g_attn16);

    // ---- prep: fp16 inputs + K-major projection weights ----
    cvt(hs, hs16, (long)NTOK_ * H_);
    cvt(Wkv_b, Wkvb16, (long)NH_ * 256 * RANK_);
    transp_f32f16<<<dim3((NH_*QHD_)/32, H_/32, 1), 256>>>(Wq, WqT, NH_*QHD_, H_, 0, 0);
    transp_f32f16<<<dim3(DATT_/32, H_/32, 1), 256>>>(Wkv_a, WkvaT, DATT_, H_, 0, 0);
    transp_f32f16<<<dim3(H_/32, H_/32, 1), 256>>>(Wo, WoT, H_, H_, 0, 0);

    // 1) q16 = hs @ Wq
    hgemm_t<__half>(hs16, WqT, q16, NTOK_, NH_*QHD_, H_, H_, H_, NH_*QHD_, 1, 1, 0,0,0,0,0,0);
    // 2) ckvraw16 = hs @ Wkv_a
    hgemm_t<__half>(hs16, WkvaT, ckvraw16, NTOK_, DATT_, H_, H_, H_, DATT_, 1, 1, 0,0,0,0,0,0);

    // 3) rms + rope
    rmsrope_kernel<<<NTOK_, 128>>>(q16, ckvraw16, pos, cosc, sinc, lnw, ckv16, keff16);

    // 4) Keff[b,h] = ckv16[b] @ q_absorb[h]^T  -> keff cols 0..127
    hgemm_t<__half>(ckv16, Wkvb16, keff16, S_, NOPE_, RANK_, RANK_, RANK_, QHD_,
          B_*NH_, NH_,
          (long)S_*RANK_, 0,
          0, (long)256*RANK_,
          (long)NH_*S_*QHD_, (long)S_*QHD_);

    // 5) VeffT[b,h] = out_absorb[h] @ ckv16[b]^T   (128 x S per bh)
    hgemm_t<__half>(Wkvb16 + (long)NOPE_*RANK_, ckv16, veffT, VDIM_, S_, RANK_,
          RANK_, RANK_, S_,
          B_*NH_, NH_,
          0, (long)256*RANK_,
          (long)S_*RANK_, 0,
          (long)NH_*VDIM_*S_, (long)VDIM_*S_);

    // 6) fused flash attention: scores + softmax + PV -> attn16
    {
        int sm = (3*128*PADQ + 2*128*PADV) * 2;   // 223232 bytes
        cudaFuncSetAttribute(flash_kernel, cudaFuncAttributeMaxDynamicSharedMemorySize, sm);
        dim3 g(NBLK, 1, B_*NH_);
        flash_kernel<<<g, 256, sm>>>(q16, keff16, veffT, attn16);
    }

    // 7) out = attn @ Wo
    hgemm_t<float>(attn16, WoT, out, NTOK_, H_, NH_*VDIM_, NH_*VDIM_, NH_*VDIM_, H_, 1, 1, 0,0,0,0,0,0);
}